// round 7
// baseline (speedup 1.0000x reference)
#include <cuda_runtime.h>

#define GRID 128
#define NTHR 256
#define Bsz 64
#define Ssz 1024
#define Tsz 300
#define Hsz 512
#define Vsz 5000
#define KQn 256

typedef unsigned long long ull;

// ---------------- device scratch ----------------
__device__ float g_k[Bsz * Ssz * KQn];
__device__ float g_v[Bsz * Ssz * Hsz];
__device__ float g_h1[2][Bsz * Hsz];
__device__ float g_c1[Bsz * Hsz];
__device__ float g_h2[2][Bsz * Hsz];
__device__ float g_c2[2][Bsz * Hsz];
__device__ float g_ctx[Bsz * Hsz];
__device__ float g_cdn[Bsz * Hsz];
__device__ float g_sc[Bsz * 1024];
__device__ float g_g1p[12 * Bsz * 2048];
__device__ float g_g2p[8 * Bsz * 2048];
__device__ float g_cdp[16 * Bsz * 512];
__device__ float g_lgp[2][Bsz * 5120];
__device__ volatile int g_flags[GRID];
__device__ volatile int g_genv;

// ---------------- shared arena ----------------
struct __align__(16) Sh {
    union {
        struct { float As[64][36]; ull Bs2[16][258]; } g;
        struct { float h2s[512]; float qs[256]; float sc[1024]; float red[8]; } a;
    } u;
    int toks[64];
};

// ---------------- grid barrier ----------------
__device__ __forceinline__ void gsync(int& gs) {
    gs++;
    __syncthreads();
    if (blockIdx.x == 0) {
        if (threadIdx.x > 0 && threadIdx.x < GRID)
            while (g_flags[threadIdx.x] < gs) __nanosleep(32);
        __syncthreads();
        if (threadIdx.x == 0) { __threadfence(); g_genv = gs; }
    } else if (threadIdx.x == 0) {
        __threadfence();
        g_flags[blockIdx.x] = gs;
        while (g_genv < gs) __nanosleep(32);
    }
    __syncthreads();
    __threadfence();
}

__device__ __forceinline__ float sigf(float x) { return 1.f / (1.f + __expf(-x)); }

__device__ __forceinline__ void fma2(ull& d, ull a, ull b) {
    asm("fma.rn.f32x2 %0, %1, %2, %3;" : "=l"(d) : "l"(a), "l"(b), "l"(d));
}
__device__ __forceinline__ float pairsum(ull x) {
    float lo, hi;
    asm("mov.b64 {%0, %1}, %2;" : "=f"(lo), "=f"(hi) : "l"(x));
    return lo + hi;
}

// ---------------- 64M x 256N GEMM tile, 8m x 8n f32x2 per thread ----------
// out[m][n] = sum_k A[m][k] * B[n][k]
// AM 0: A row-major stride arow. AM 1: [emb[tok]|A1|A2] each 512.
// AM 2: [A0(512)|A1(512+)]. B row n: k<segB -> B0(len L0) else B1(len L1).
template <int AM>
__device__ __forceinline__ void gemm8(
    const float* __restrict__ A0, const float* __restrict__ A1,
    const float* __restrict__ A2, long arow,
    const float* __restrict__ B0, long L0, int segB,
    const float* __restrict__ B1, long L1,
    int nbase, int Nmax, int kbeg, int kend,
    float* __restrict__ outp, long OS, const float* __restrict__ bias,
    const int* __restrict__ yy, int t, Sh& sh)
{
    const int tid = threadIdx.x;
    const int tn = tid & 31;
    const int mt8 = (tid >> 5) * 8;          // warp-uniform m base
    const int ar = tid >> 2;                 // A fill row 0..63
    const int akc = (tid & 3) * 8;           // A fill k-col {0,8,16,24}
    const int bkid = tid & 7;                // B fill k-quad 0..7
    const int bn0 = tid >> 3;                // B fill n base 0..31

    if (AM == 1) {
        if (tid < 64) sh.toks[tid] = (t == 0) ? 0 : yy[tid * Tsz + (t - 1)];
        __syncthreads();
    }

    ull acc[8][8];
#pragma unroll
    for (int i = 0; i < 8; i++)
#pragma unroll
        for (int j = 0; j < 8; j++) acc[i][j] = 0ULL;

    for (int kb = kbeg; kb < kend; kb += 32) {
        // ---- A fill: 64 x 32 (2 float4 per thread) ----
#pragma unroll
        for (int p = 0; p < 2; p++) {
            int kc = akc + p * 4;
            int k = kb + kc;
            const float* rp;
            if (AM == 0)      rp = A0 + (long)ar * arow + k;
            else if (AM == 1) rp = (k < 512)  ? A0 + (long)sh.toks[ar] * 512 + k
                             : (k < 1024) ? A1 + ar * 512 + (k - 512)
                                          : A2 + ar * 512 + (k - 1024);
            else              rp = (k < 512) ? A0 + ar * 512 + k
                                             : A1 + ar * 512 + (k - 512);
            *(float4*)&sh.u.g.As[ar][kc] = *(const float4*)rp;
        }
        // ---- B fill: 256 x 32, transposed to k-pair-major (8 float4/thread) ----
#pragma unroll
        for (int p = 0; p < 8; p++) {
            int n = bn0 + 32 * p;
            int ng = nbase + n;
            int k = kb + bkid * 4;
            float4 v = make_float4(0.f, 0.f, 0.f, 0.f);
            if (ng < Nmax) {
                const float* rp = (k < segB) ? B0 + (long)ng * L0 + k
                                             : B1 + (long)ng * L1 + (k - segB);
                v = *(const float4*)rp;
            }
            int kp = bkid * 2;
            *(float2*)&sh.u.g.Bs2[kp][n]     = make_float2(v.x, v.y);
            *(float2*)&sh.u.g.Bs2[kp + 1][n] = make_float2(v.z, v.w);
        }
        __syncthreads();
#pragma unroll
        for (int kq = 0; kq < 8; kq++) {
            ulonglong2 a2[8];
#pragma unroll
            for (int i = 0; i < 8; i++)
                a2[i] = *(const ulonglong2*)&sh.u.g.As[mt8 + i][4 * kq];
#pragma unroll
            for (int h = 0; h < 2; h++) {
                int kp = 2 * kq + h;
                ull b[8];
#pragma unroll
                for (int j = 0; j < 4; j++) {
                    ulonglong2 t2 = *(const ulonglong2*)&sh.u.g.Bs2[kp][64 * j + 2 * tn];
                    b[2 * j] = t2.x; b[2 * j + 1] = t2.y;
                }
#pragma unroll
                for (int i = 0; i < 8; i++) {
                    ull av = h ? a2[i].y : a2[i].x;
#pragma unroll
                    for (int j = 0; j < 8; j++) fma2(acc[i][j], av, b[j]);
                }
            }
        }
        __syncthreads();
    }

#pragma unroll
    for (int i = 0; i < 8; i++) {
        long m = mt8 + i;
#pragma unroll
        for (int j = 0; j < 4; j++) {
            int n = nbase + 64 * j + 2 * tn;
            if (n < Nmax) {
                float s0 = pairsum(acc[i][2 * j]);
                float s1 = pairsum(acc[i][2 * j + 1]);
                if (bias) { s0 += bias[n]; s1 += bias[n + 1]; }
                *(float2*)&outp[m * OS + n] = make_float2(s0, s1);
            }
        }
    }
    __syncthreads();
}

// ---------------- logits reduce: out[:, ts, :] = sum lgp + bcls --------------
__device__ __forceinline__ void logits_reduce(int ts, const float* __restrict__ bcls,
                                              float* __restrict__ out) {
    int gid = blockIdx.x * NTHR + threadIdx.x;
    for (int e = gid; e < Bsz * Vsz; e += GRID * NTHR) {
        int m = e / Vsz, n = e - m * Vsz;
        out[((long)m * Tsz + ts) * Vsz + n] =
            g_lgp[0][m * 5120 + n] + g_lgp[1][m * 5120 + n] + bcls[n];
    }
}

// ---------------- cdn reduce: g_cdn = relu(sum cdp + bcdn) ------------------
__device__ __forceinline__ void cdn_reduce(const float* __restrict__ bcdn) {
    int gid = blockIdx.x * NTHR + threadIdx.x;   // 32768 = exactly Bsz*Hsz
    float s = bcdn[gid & 511];
#pragma unroll
    for (int ks = 0; ks < 16; ks++) s += g_cdp[ks * 32768 + gid];
    g_cdn[gid] = fmaxf(s, 0.f);
}

// ---------------- persistent mega-kernel ----------------
__global__ void __launch_bounds__(NTHR, 1)
mega(const float* __restrict__ enc, const int* __restrict__ y,
     const float* __restrict__ emb,
     const float* __restrict__ Wq, const float* __restrict__ bq,
     const float* __restrict__ Wk, const float* __restrict__ bk,
     const float* __restrict__ Wv, const float* __restrict__ bv,
     const float* __restrict__ Wih1, const float* __restrict__ bih1,
     const float* __restrict__ Whh1, const float* __restrict__ bhh1,
     const float* __restrict__ Wih2, const float* __restrict__ bih2,
     const float* __restrict__ Whh2, const float* __restrict__ bhh2,
     const float* __restrict__ Wcdn, const float* __restrict__ bcdn,
     const float* __restrict__ bcls, float* __restrict__ out)
{
    __shared__ Sh sh;
    const int tid = threadIdx.x;
    const int bx = blockIdx.x;
    int gs = g_genv;

    // ---- init: zero recurrent state ----
    for (int i = bx * NTHR + tid; i < 6 * Bsz * Hsz; i += GRID * NTHR) {
        int a = i >> 15, j = i & 32767;
        float* p = a == 0 ? g_h1[0] : a == 1 ? g_c1 : a == 2 ? g_h2[0]
                 : a == 3 ? g_c2[0] : a == 4 ? g_ctx : g_c2[1];
        p[j] = 0.f;
    }
    // ---- kv projection: 1024 K units + 2048 V units ----
    for (int j = bx; j < 3072; j += GRID) {
        if (j < 1024) {
            gemm8<0>(enc + (long)j * 64 * 512, nullptr, nullptr, 512,
                     Wk, 512, 1 << 30, nullptr, 0,
                     0, 1 << 30, 0, 512,
                     g_k + (long)j * 64 * KQn, KQn, bk, nullptr, 0, sh);
        } else {
            int v = j - 1024;
            int mt_ = v >> 1, nt_ = v & 1;
            gemm8<0>(enc + (long)mt_ * 64 * 512, nullptr, nullptr, 512,
                     Wv, 512, 1 << 30, nullptr, 0,
                     nt_ * 256, 1 << 30, 0, 512,
                     g_v + (long)mt_ * 64 * Hsz, Hsz, bv, nullptr, 0, sh);
        }
    }
    gsync(gs);

    for (int t = 0; t < Tsz; t++) {
        const float* h1o = g_h1[t & 1];
        float*       h1n = g_h1[(t + 1) & 1];
        const float* h2o = g_h2[t & 1];
        float*       h2n = g_h2[(t + 1) & 1];
        const float* c2o = g_c2[t & 1];
        float*       c2n = g_c2[(t + 1) & 1];

        // ---- P1: LSTM1 (96 blk: 8nt x 12sk, k=128) || cdn(t-1) (32 blk) ----
        if (bx < 96) {
            int ntile = bx / 12, ks = bx % 12;
            gemm8<1>(emb, g_ctx, h1o, 0,
                     Wih1, 1024, 1024, Whh1, 512,
                     ntile * 256, 1 << 30, ks * 128, ks * 128 + 128,
                     g_g1p + (long)ks * 131072, 2048, nullptr, y, t, sh);
        } else if (t > 0) {
            int u = bx - 96, ntile = u >> 4, ks = u & 15;  // 2nt x 16sk, k=64
            gemm8<2>(h2o, g_ctx, nullptr, 0,
                     Wcdn, 1024, 1 << 30, nullptr, 0,
                     ntile * 256, 1 << 30, ks * 64, ks * 64 + 64,
                     g_cdp + (long)ks * 32768, 512, nullptr, nullptr, 0, sh);
        }
        gsync(gs);

        // ---- P2: cell1 + cdn-reduce(t-1) + logits-reduce(t-2) ----
        {
            int gid = bx * NTHR + tid;         // exactly 32768
            int b = gid >> 9, u = gid & 511;
            float gt[4];
#pragma unroll
            for (int g = 0; g < 4; g++) {
                int n = g * 512 + u;
                float s = bih1[n] + bhh1[n];
#pragma unroll
                for (int ks = 0; ks < 12; ks++)
                    s += g_g1p[ks * 131072 + b * 2048 + n];
                gt[g] = s;
            }
            float cn = sigf(gt[1]) * g_c1[gid] + sigf(gt[0]) * tanhf(gt[2]);
            g_c1[gid] = cn;
            h1n[gid] = sigf(gt[3]) * tanhf(cn);
            if (t > 0) cdn_reduce(bcdn);
            if (t > 1) logits_reduce(t - 2, bcls, out);
            gsync(gs);
        }

        // ---- P3: LSTM2 (64 blk: 8nt x 8sk, k=128) || logits(t-1) (40 blk) ----
        if (bx < 64) {
            int ntile = bx >> 3, ks = bx & 7;
            gemm8<2>(h1n, h2o, nullptr, 0,
                     Wih2, 512, 512, Whh2, 512,
                     ntile * 256, 1 << 30, ks * 128, ks * 128 + 128,
                     g_g2p + (long)ks * 131072, 2048, nullptr, nullptr, 0, sh);
        } else if (t > 0 && bx < 104) {
            int u = bx - 64, tile = u >> 1, kh = u & 1;  // 20nt x 2sk, k=256
            gemm8<0>(g_cdn, nullptr, nullptr, 512,
                     emb, 512, 1 << 30, nullptr, 0,
                     tile * 256, Vsz, kh * 256, kh * 256 + 256,
                     g_lgp[kh], 5120, nullptr, nullptr, 0, sh);
        }
        gsync(gs);

        // ---- P4a: cell2 + q-proj + half-S scores (2 blocks per batch) ----
        {
            int b = bx >> 1, hs = bx & 1, lane = tid & 31, w = tid >> 5;
            // cell2 (redundant in both siblings; only hs==0 writes)
#pragma unroll
            for (int p = 0; p < 2; p++) {
                int u = tid + 256 * p;
                float gt[4];
#pragma unroll
                for (int g = 0; g < 4; g++) {
                    int n = g * 512 + u;
                    float s = bih2[n] + bhh2[n];
#pragma unroll
                    for (int ks = 0; ks < 8; ks++)
                        s += g_g2p[ks * 131072 + b * 2048 + n];
                    gt[g] = s;
                }
                float cn = sigf(gt[1]) * c2o[b * 512 + u] + sigf(gt[0]) * tanhf(gt[2]);
                float h = sigf(gt[3]) * tanhf(cn);
                if (hs == 0) { c2n[b * 512 + u] = cn; h2n[b * 512 + u] = h; }
                sh.u.a.h2s[u] = h;
            }
            __syncthreads();
            // q projection: 8 warps x 32 outputs (scale folded)
            {
                const float4* h24 = (const float4*)sh.u.a.h2s;
                float4 hv0 = h24[lane], hv1 = h24[32 + lane],
                       hv2 = h24[64 + lane], hv3 = h24[96 + lane];
#pragma unroll 2
                for (int jj = 0; jj < 32; jj++) {
                    int j = w * 32 + jj;
                    const float4* wr = (const float4*)(Wq + (long)j * 512);
                    float4 w0 = wr[lane], w1 = wr[32 + lane],
                           w2 = wr[64 + lane], w3 = wr[96 + lane];
                    float s = hv0.x * w0.x + hv0.y * w0.y + hv0.z * w0.z + hv0.w * w0.w
                            + hv1.x * w1.x + hv1.y * w1.y + hv1.z * w1.z + hv1.w * w1.w
                            + hv2.x * w2.x + hv2.y * w2.y + hv2.z * w2.z + hv2.w * w2.w
                            + hv3.x * w3.x + hv3.y * w3.y + hv3.z * w3.z + hv3.w * w3.w;
#pragma unroll
                    for (int o = 16; o; o >>= 1) s += __shfl_xor_sync(~0u, s, o);
                    if (lane == 0) sh.u.a.qs[j] = (s + bq[j]) * 0.0625f;
                }
            }
            __syncthreads();
            // scores: 512 rows (this half), warp per row group of 64
            {
                const float4* q4 = (const float4*)sh.u.a.qs;
                float4 qr0 = q4[lane], qr1 = q4[32 + lane];
                int rbase = hs * 512 + w * 64;
#pragma unroll 4
                for (int i = 0; i < 64; i++) {
                    int row = rbase + i;
                    const float4* kr = (const float4*)(g_k + ((long)b * 1024 + row) * 256);
                    float4 k0 = kr[lane], k1 = kr[32 + lane];
                    float a = qr0.x * k0.x + qr0.y * k0.y + qr0.z * k0.z + qr0.w * k0.w
                            + qr1.x * k1.x + qr1.y * k1.y + qr1.z * k1.z + qr1.w * k1.w;
#pragma unroll
                    for (int o = 16; o; o >>= 1) a += __shfl_xor_sync(~0u, a, o);
                    if (lane == 0) g_sc[b * 1024 + row] = a;
                }
            }
            gsync(gs);
        }

        // ---- P4b: softmax (redundant per sibling) + half-V context ----
        {
            int b = bx >> 1, hc = bx & 1, lane = tid & 31, w = tid >> 5;
            float* sc = sh.u.a.sc;
            float* red = sh.u.a.red;
#pragma unroll
            for (int i = 0; i < 4; i++)
                sc[tid + i * 256] = g_sc[b * 1024 + tid + i * 256];
            __syncthreads();
            float mx = fmaxf(fmaxf(sc[tid], sc[tid + 256]),
                             fmaxf(sc[tid + 512], sc[tid + 768]));
#pragma unroll
            for (int o = 16; o; o >>= 1) mx = fmaxf(mx, __shfl_xor_sync(~0u, mx, o));
            if (lane == 0) red[w] = mx;
            __syncthreads();
            mx = fmaxf(fmaxf(fmaxf(red[0], red[1]), fmaxf(red[2], red[3])),
                       fmaxf(fmaxf(red[4], red[5]), fmaxf(red[6], red[7])));
            __syncthreads();
            float ls = 0.f;
#pragma unroll
            for (int i = 0; i < 4; i++) {
                float e = __expf(sc[tid + i * 256] - mx);
                sc[tid + i * 256] = e;
                ls += e;
            }
#pragma unroll
            for (int o = 16; o; o >>= 1) ls += __shfl_xor_sync(~0u, ls, o);
            if (lane == 0) red[w] = ls;
            __syncthreads();
            float inv = 1.f / (red[0] + red[1] + red[2] + red[3]
                             + red[4] + red[5] + red[6] + red[7]);
            // context: 256 cols (this half), 1 col per thread
            int col = hc * 256 + tid;
            const float* vp = g_v + (long)b * (Ssz * Hsz) + col;
            float a0 = 0.f, a1 = 0.f, a2 = 0.f, a3 = 0.f;
            float a4 = 0.f, a5 = 0.f, a6 = 0.f, a7 = 0.f;
#pragma unroll 4
            for (int s2 = 0; s2 < 1024; s2 += 8) {
                a0 += sc[s2]     * vp[(long)(s2)     * 512];
                a1 += sc[s2 + 1] * vp[(long)(s2 + 1) * 512];
                a2 += sc[s2 + 2] * vp[(long)(s2 + 2) * 512];
                a3 += sc[s2 + 3] * vp[(long)(s2 + 3) * 512];
                a4 += sc[s2 + 4] * vp[(long)(s2 + 4) * 512];
                a5 += sc[s2 + 5] * vp[(long)(s2 + 5) * 512];
                a6 += sc[s2 + 6] * vp[(long)(s2 + 6) * 512];
                a7 += sc[s2 + 7] * vp[(long)(s2 + 7) * 512];
            }
            g_ctx[b * 512 + col] =
                (((a0 + a1) + (a2 + a3)) + ((a4 + a5) + (a6 + a7))) * inv;
            gsync(gs);
        }
    }

    // ---- epilogue: cdn(299), reduces, logits(299) ----
    {
        const float* h2last = g_h2[Tsz & 1];
        if (bx >= 96) {
            int u = bx - 96, ntile = u >> 4, ks = u & 15;
            gemm8<2>(h2last, g_ctx, nullptr, 0,
                     Wcdn, 1024, 1 << 30, nullptr, 0,
                     ntile * 256, 1 << 30, ks * 64, ks * 64 + 64,
                     g_cdp + (long)ks * 32768, 512, nullptr, nullptr, 0, sh);
        }
        gsync(gs);
        cdn_reduce(bcdn);
        logits_reduce(Tsz - 2, bcls, out);
        gsync(gs);
        if (bx < 40) {
            int tile = bx >> 1, kh = bx & 1;
            gemm8<0>(g_cdn, nullptr, nullptr, 512,
                     emb, 512, 1 << 30, nullptr, 0,
                     tile * 256, Vsz, kh * 256, kh * 256 + 256,
                     g_lgp[kh], 5120, nullptr, nullptr, 0, sh);
        }
        gsync(gs);
        logits_reduce(Tsz - 1, bcls, out);
    }
}

extern "C" void kernel_launch(void* const* d_in, const int* in_sizes, int n_in,
                              void* d_out, int out_size) {
    mega<<<GRID, NTHR>>>(
        (const float*)d_in[0],  (const int*)d_in[1],   (const float*)d_in[2],
        (const float*)d_in[3],  (const float*)d_in[4],
        (const float*)d_in[5],  (const float*)d_in[6],
        (const float*)d_in[7],  (const float*)d_in[8],
        (const float*)d_in[9],  (const float*)d_in[10],
        (const float*)d_in[11], (const float*)d_in[12],
        (const float*)d_in[13], (const float*)d_in[14],
        (const float*)d_in[15], (const float*)d_in[16],
        (const float*)d_in[17], (const float*)d_in[18],
        (const float*)d_in[19], (float*)d_out);
}

// round 8
// speedup vs baseline: 1.2675x; 1.2675x over previous
#include <cuda_runtime.h>

#define GRID 128
#define NTHR 512
#define Bsz 64
#define Ssz 1024
#define Tsz 300
#define Hsz 512
#define Vsz 5000
#define KQn 256

typedef unsigned long long ull;

// ---------------- device scratch ----------------
__device__ float g_k[Bsz * Ssz * KQn];
__device__ float g_v[Bsz * Ssz * Hsz];
__device__ float g_h1[2][Bsz * Hsz];
__device__ float g_c1[Bsz * Hsz];
__device__ float g_h2[2][Bsz * Hsz];
__device__ float g_c2[2][Bsz * Hsz];
__device__ float g_ctx[Bsz * Hsz];
__device__ float g_cdn[Bsz * Hsz];
__device__ float g_sc[Bsz * 1024];
__device__ float g_g1p[6 * Bsz * 2048];
__device__ float g_g2p[4 * Bsz * 2048];
__device__ float g_cdp[8 * Bsz * 512];
__device__ float g_lgp[2][Bsz * 5120];
__device__ volatile int g_flags[GRID];
__device__ volatile int g_genv;

// ---------------- shared arena ----------------
struct __align__(16) Sh {
    union {
        struct { float As[64][36]; float Bs[128][36]; } g;
        struct { float h2s[512]; float qs[256]; float sc[1024];
                 float red[16]; float part[2][256]; } a;
    } u;
    int toks[64];
};

// ---------------- grid barrier ----------------
__device__ __forceinline__ void gsync(int& gs) {
    gs++;
    __syncthreads();
    if (blockIdx.x == 0) {
        if (threadIdx.x > 0 && threadIdx.x < GRID)
            while (g_flags[threadIdx.x] < gs) __nanosleep(32);
        __syncthreads();
        if (threadIdx.x == 0) { __threadfence(); g_genv = gs; }
    } else if (threadIdx.x == 0) {
        __threadfence();
        g_flags[blockIdx.x] = gs;
        while (g_genv < gs) __nanosleep(32);
    }
    __syncthreads();
    __threadfence();
}

__device__ __forceinline__ float sigf(float x) { return 1.f / (1.f + __expf(-x)); }

__device__ __forceinline__ void fma2(ull& d, ull a, ull b) {
    asm("fma.rn.f32x2 %0, %1, %2, %3;" : "=l"(d) : "l"(a), "l"(b), "l"(d));
}
__device__ __forceinline__ float pairsum(ull x) {
    float lo, hi;
    asm("mov.b64 {%0, %1}, %2;" : "=f"(lo), "=f"(hi) : "l"(x));
    return lo + hi;
}

// ---------------- 64M x 128N GEMM tile, f32x2, register-prefetched ---------
// out[m][n] = sum_k A[m][k] * B[n][k]
// AM 0: A row-major stride arow. AM 1: [emb[tok]|A1|A2] each 512.
// AM 2: [A0(512)|A1(512+)]. B row n: k<segB -> B0(len L0) else B1(len L1).
template <int AM>
__device__ __forceinline__ void gemm2(
    const float* __restrict__ A0, const float* __restrict__ A1,
    const float* __restrict__ A2, long arow,
    const float* __restrict__ B0, long L0, int segB,
    const float* __restrict__ B1, long L1,
    int nbase, int Nmax, int kbeg, int kend,
    float* __restrict__ outp, long OS, const float* __restrict__ bias,
    const int* __restrict__ yy, int t, Sh& sh)
{
    const int tid = threadIdx.x;
    const int nt = tid & 31;
    const int mt = tid >> 5;                 // warp id (uniform)
    const int ar = tid >> 3;                 // fill row 0..63
    const int kq4 = (tid & 7) * 4;           // fill k col

    if (AM == 1) {
        if (tid < 64) sh.toks[tid] = (t == 0) ? 0 : yy[tid * Tsz + (t - 1)];
        __syncthreads();
    }

    ull acc[4][4];
#pragma unroll
    for (int i = 0; i < 4; i++)
#pragma unroll
        for (int j = 0; j < 4; j++) acc[i][j] = 0ULL;

    float4 pa, pb0, pb1;
    // prefetch helpers (inline lambdas keep reg pressure local)
    auto loadA = [&](int kb, float4& d) {
        int k = kb + kq4;
        const float* rp;
        if (AM == 0)      rp = A0 + (long)ar * arow + k;
        else if (AM == 1) rp = (k < 512)  ? A0 + (long)sh.toks[ar] * 512 + k
                         : (k < 1024) ? A1 + ar * 512 + (k - 512)
                                      : A2 + ar * 512 + (k - 1024);
        else              rp = (k < 512) ? A0 + ar * 512 + k
                                         : A1 + ar * 512 + (k - 512);
        d = *(const float4*)rp;
    };
    auto loadB = [&](int kb, int n, float4& d) {
        int ng = nbase + n;
        int k = kb + kq4;
        d = make_float4(0.f, 0.f, 0.f, 0.f);
        if (ng < Nmax) {
            const float* rp = (k < segB) ? B0 + (long)ng * L0 + k
                                         : B1 + (long)ng * L1 + (k - segB);
            d = *(const float4*)rp;
        }
    };

    loadA(kbeg, pa);
    loadB(kbeg, ar, pb0);
    loadB(kbeg, ar + 64, pb1);

    for (int kb = kbeg; kb < kend; kb += 32) {
        __syncthreads();
        *(float4*)&sh.u.g.As[ar][kq4]      = pa;
        *(float4*)&sh.u.g.Bs[ar][kq4]      = pb0;
        *(float4*)&sh.u.g.Bs[ar + 64][kq4] = pb1;
        __syncthreads();
        if (kb + 32 < kend) {
            loadA(kb + 32, pa);
            loadB(kb + 32, ar, pb0);
            loadB(kb + 32, ar + 64, pb1);
        }
#pragma unroll
        for (int kq = 0; kq < 8; kq++) {
            ull a0[4], a1[4], b0[4], b1[4];
#pragma unroll
            for (int j = 0; j < 4; j++) {
                ulonglong2 tb = *(const ulonglong2*)&sh.u.g.Bs[nt + 32 * j][4 * kq];
                b0[j] = tb.x; b1[j] = tb.y;
            }
#pragma unroll
            for (int i = 0; i < 4; i++) {
                ulonglong2 ta = *(const ulonglong2*)&sh.u.g.As[mt * 4 + i][4 * kq];
                a0[i] = ta.x; a1[i] = ta.y;
            }
#pragma unroll
            for (int i = 0; i < 4; i++)
#pragma unroll
                for (int j = 0; j < 4; j++) {
                    fma2(acc[i][j], a0[i], b0[j]);
                    fma2(acc[i][j], a1[i], b1[j]);
                }
        }
    }
    __syncthreads();

#pragma unroll
    for (int i = 0; i < 4; i++) {
        long m = mt * 4 + i;
#pragma unroll
        for (int j = 0; j < 4; j++) {
            int n = nbase + nt + 32 * j;
            if (n < Nmax) {
                float s = pairsum(acc[i][j]);
                if (bias) s += bias[n];
                outp[m * OS + n] = s;
            }
        }
    }
    __syncthreads();
}

// ---------------- persistent mega-kernel ----------------
__global__ void __launch_bounds__(NTHR, 1)
mega(const float* __restrict__ enc, const int* __restrict__ y,
     const float* __restrict__ emb,
     const float* __restrict__ Wq, const float* __restrict__ bq,
     const float* __restrict__ Wk, const float* __restrict__ bk,
     const float* __restrict__ Wv, const float* __restrict__ bv,
     const float* __restrict__ Wih1, const float* __restrict__ bih1,
     const float* __restrict__ Whh1, const float* __restrict__ bhh1,
     const float* __restrict__ Wih2, const float* __restrict__ bih2,
     const float* __restrict__ Whh2, const float* __restrict__ bhh2,
     const float* __restrict__ Wcdn, const float* __restrict__ bcdn,
     const float* __restrict__ bcls, float* __restrict__ out)
{
    __shared__ Sh sh;
    const int tid = threadIdx.x;
    const int bx = blockIdx.x;
    int gs = g_genv;

    // ---- init: zero recurrent state ----
    for (int i = bx * NTHR + tid; i < 6 * Bsz * Hsz; i += GRID * NTHR) {
        int a = i >> 15, j = i & 32767;
        float* p = a == 0 ? g_h1[0] : a == 1 ? g_c1 : a == 2 ? g_h2[0]
                 : a == 3 ? g_c2[0] : a == 4 ? g_ctx : g_c2[1];
        p[j] = 0.f;
    }
    // ---- kv projection ----
    for (int j = bx; j < 6144; j += GRID) {
        if (j < 2048) {
            int mt_ = j >> 1, nt_ = j & 1;
            gemm2<0>(enc + (long)mt_ * 64 * 512, nullptr, nullptr, 512,
                     Wk, 512, 1 << 30, nullptr, 0,
                     nt_ * 128, 1 << 30, 0, 512,
                     g_k + (long)mt_ * 64 * KQn, KQn, bk, nullptr, 0, sh);
        } else {
            int v = j - 2048;
            int mt_ = v >> 2, nt_ = v & 3;
            gemm2<0>(enc + (long)mt_ * 64 * 512, nullptr, nullptr, 512,
                     Wv, 512, 1 << 30, nullptr, 0,
                     nt_ * 128, 1 << 30, 0, 512,
                     g_v + (long)mt_ * 64 * Hsz, Hsz, bv, nullptr, 0, sh);
        }
    }
    gsync(gs);

    for (int t = 0; t < Tsz; t++) {
        const float* h1o = g_h1[t & 1];
        float*       h1n = g_h1[(t + 1) & 1];
        const float* h2o = g_h2[t & 1];
        float*       h2n = g_h2[(t + 1) & 1];
        const float* c2o = g_c2[t & 1];
        float*       c2n = g_c2[(t + 1) & 1];

        // ---- P1: LSTM1 (blk 0-95: 16nt x 6sk, k=256) || cdn(t-1) (96-127) --
        if (bx < 96) {
            int ntile = bx / 6, ks = bx % 6;
            gemm2<1>(emb, g_ctx, h1o, 0,
                     Wih1, 1024, 1024, Whh1, 512,
                     ntile * 128, 1 << 30, ks * 256, ks * 256 + 256,
                     g_g1p + (long)ks * 131072, 2048, nullptr, y, t, sh);
        } else if (t > 0) {
            int u = bx - 96, ntile = u >> 3, ks = u & 7;  // 4nt x 8sk, k=128
            gemm2<2>(h2o, g_ctx, nullptr, 0,
                     Wcdn, 1024, 1 << 30, nullptr, 0,
                     ntile * 128, 1 << 30, ks * 128, ks * 128 + 128,
                     g_cdp + (long)ks * 32768, 512, nullptr, nullptr, 0, sh);
        }
        gsync(gs);

        // ---- P2: cell1 (blk 0-63) + cdn-red(t-1) (64-127) + lg-red(t-2) ----
        {
            int gid = bx * NTHR + tid;
            if (gid < 32768) {
                int b = gid >> 9, u = gid & 511;
                float gt[4];
#pragma unroll
                for (int g = 0; g < 4; g++) {
                    int n = g * 512 + u;
                    float s = bih1[n] + bhh1[n];
#pragma unroll
                    for (int ks = 0; ks < 6; ks++)
                        s += g_g1p[ks * 131072 + b * 2048 + n];
                    gt[g] = s;
                }
                float cn = sigf(gt[1]) * g_c1[gid] + sigf(gt[0]) * tanhf(gt[2]);
                g_c1[gid] = cn;
                h1n[gid] = sigf(gt[3]) * tanhf(cn);
            } else if (t > 0) {
                int idx = gid - 32768;
                float s = bcdn[idx & 511];
#pragma unroll
                for (int ks = 0; ks < 8; ks++) s += g_cdp[ks * 32768 + idx];
                g_cdn[idx] = fmaxf(s, 0.f);
            }
            if (t > 1) {
                for (int e = gid; e < Bsz * Vsz; e += GRID * NTHR) {
                    int m = e / Vsz, n = e - m * Vsz;
                    out[((long)m * Tsz + (t - 2)) * Vsz + n] =
                        g_lgp[0][m * 5120 + n] + g_lgp[1][m * 5120 + n] + bcls[n];
                }
            }
            gsync(gs);
        }

        // ---- P3: LSTM2 (blk 0-63: 16nt x 4sk, k=256) || logits(t-1) kh0 ----
        if (bx < 64) {
            int ntile = bx >> 2, ks = bx & 3;
            gemm2<2>(h1n, h2o, nullptr, 0,
                     Wih2, 512, 512, Whh2, 512,
                     ntile * 128, 1 << 30, ks * 256, ks * 256 + 256,
                     g_g2p + (long)ks * 131072, 2048, nullptr, nullptr, 0, sh);
        } else if (t > 0 && bx < 104) {
            int tile = bx - 64;
            gemm2<0>(g_cdn, nullptr, nullptr, 512,
                     emb, 512, 1 << 30, nullptr, 0,
                     tile * 128, Vsz, 0, 256,
                     g_lgp[0], 5120, nullptr, nullptr, 0, sh);
        }
        gsync(gs);

        // ---- P4a: cell2+q+scores (blk 0-63) || logits(t-1) kh1 (64-103) ----
        if (bx < 64) {
            int b = bx, lane = tid & 31, w = tid >> 5;
            // cell2: one unit per thread
            {
                int u = tid;
                float gt[4];
#pragma unroll
                for (int g = 0; g < 4; g++) {
                    int n = g * 512 + u;
                    float s = bih2[n] + bhh2[n];
#pragma unroll
                    for (int ks = 0; ks < 4; ks++)
                        s += g_g2p[ks * 131072 + b * 2048 + n];
                    gt[g] = s;
                }
                float cn = sigf(gt[1]) * c2o[b * 512 + u] + sigf(gt[0]) * tanhf(gt[2]);
                float h = sigf(gt[3]) * tanhf(cn);
                c2n[b * 512 + u] = cn;
                h2n[b * 512 + u] = h;
                sh.u.a.h2s[u] = h;
            }
            __syncthreads();
            // q projection: 16 warps x 16 outputs (scale folded)
            {
                const float4* h24 = (const float4*)sh.u.a.h2s;
                float4 hv0 = h24[lane], hv1 = h24[32 + lane],
                       hv2 = h24[64 + lane], hv3 = h24[96 + lane];
#pragma unroll 2
                for (int jj = 0; jj < 16; jj++) {
                    int j = w * 16 + jj;
                    const float4* wr = (const float4*)(Wq + (long)j * 512);
                    float4 w0 = wr[lane], w1 = wr[32 + lane],
                           w2 = wr[64 + lane], w3 = wr[96 + lane];
                    float s = hv0.x * w0.x + hv0.y * w0.y + hv0.z * w0.z + hv0.w * w0.w
                            + hv1.x * w1.x + hv1.y * w1.y + hv1.z * w1.z + hv1.w * w1.w
                            + hv2.x * w2.x + hv2.y * w2.y + hv2.z * w2.z + hv2.w * w2.w
                            + hv3.x * w3.x + hv3.y * w3.y + hv3.z * w3.z + hv3.w * w3.w;
#pragma unroll
                    for (int o = 16; o; o >>= 1) s += __shfl_xor_sync(~0u, s, o);
                    if (lane == 0) sh.u.a.qs[j] = (s + bq[j]) * 0.0625f;
                }
            }
            __syncthreads();
            // scores: full S, 16 warps x 64 rows
            {
                const float4* q4 = (const float4*)sh.u.a.qs;
                float4 qr0 = q4[lane], qr1 = q4[32 + lane];
                int rbase = w * 64;
#pragma unroll 4
                for (int i = 0; i < 64; i++) {
                    int row = rbase + i;
                    const float4* kr = (const float4*)(g_k + ((long)b * 1024 + row) * 256);
                    float4 k0 = kr[lane], k1 = kr[32 + lane];
                    float a = qr0.x * k0.x + qr0.y * k0.y + qr0.z * k0.z + qr0.w * k0.w
                            + qr1.x * k1.x + qr1.y * k1.y + qr1.z * k1.z + qr1.w * k1.w;
#pragma unroll
                    for (int o = 16; o; o >>= 1) a += __shfl_xor_sync(~0u, a, o);
                    if (lane == 0) g_sc[b * 1024 + row] = a;
                }
            }
        } else if (t > 0 && bx < 104) {
            int tile = bx - 64;
            gemm2<0>(g_cdn, nullptr, nullptr, 512,
                     emb, 512, 1 << 30, nullptr, 0,
                     tile * 128, Vsz, 256, 512,
                     g_lgp[1], 5120, nullptr, nullptr, 0, sh);
        }
        gsync(gs);

        // ---- P4b: softmax + half-V context (2 blocks per batch) ----
        {
            int b = bx >> 1, hc = bx & 1, lane = tid & 31, w = tid >> 5;
            float* sc = sh.u.a.sc;
            float* red = sh.u.a.red;
            sc[tid]       = g_sc[b * 1024 + tid];
            sc[tid + 512] = g_sc[b * 1024 + tid + 512];
            __syncthreads();
            float mx = fmaxf(sc[tid], sc[tid + 512]);
#pragma unroll
            for (int o = 16; o; o >>= 1) mx = fmaxf(mx, __shfl_xor_sync(~0u, mx, o));
            if (lane == 0) red[w] = mx;
            __syncthreads();
            mx = red[0];
#pragma unroll
            for (int i = 1; i < 16; i++) mx = fmaxf(mx, red[i]);
            __syncthreads();
            float e0 = __expf(sc[tid] - mx);
            float e1 = __expf(sc[tid + 512] - mx);
            sc[tid] = e0; sc[tid + 512] = e1;
            float ls = e0 + e1;
#pragma unroll
            for (int o = 16; o; o >>= 1) ls += __shfl_xor_sync(~0u, ls, o);
            if (lane == 0) red[w] = ls;
            __syncthreads();
            float tot = 0.f;
#pragma unroll
            for (int i = 0; i < 16; i++) tot += red[i];
            float inv = 1.f / tot;
            // context: col = hc*256 + (tid&255), s-half = tid>>8
            int c = tid & 255, shalf = tid >> 8;
            int col = hc * 256 + c;
            const float* vp = g_v + (long)b * (Ssz * Hsz) + (long)shalf * 512 * 512 + col;
            const float* scp = sc + shalf * 512;
            float a0 = 0.f, a1 = 0.f, a2 = 0.f, a3 = 0.f;
            float a4 = 0.f, a5 = 0.f, a6 = 0.f, a7 = 0.f;
#pragma unroll 4
            for (int s2 = 0; s2 < 512; s2 += 8) {
                a0 += scp[s2]     * vp[(long)(s2)     * 512];
                a1 += scp[s2 + 1] * vp[(long)(s2 + 1) * 512];
                a2 += scp[s2 + 2] * vp[(long)(s2 + 2) * 512];
                a3 += scp[s2 + 3] * vp[(long)(s2 + 3) * 512];
                a4 += scp[s2 + 4] * vp[(long)(s2 + 4) * 512];
                a5 += scp[s2 + 5] * vp[(long)(s2 + 5) * 512];
                a6 += scp[s2 + 6] * vp[(long)(s2 + 6) * 512];
                a7 += scp[s2 + 7] * vp[(long)(s2 + 7) * 512];
            }
            sh.u.a.part[shalf][c] =
                ((a0 + a1) + (a2 + a3)) + ((a4 + a5) + (a6 + a7));
            __syncthreads();
            if (tid < 256)
                g_ctx[b * 512 + hc * 256 + tid] =
                    (sh.u.a.part[0][tid] + sh.u.a.part[1][tid]) * inv;
            gsync(gs);
        }
    }

    // ---- epilogue ----
    {
        const float* h2last = g_h2[Tsz & 1];
        // E1: cdn(299) on blocks 96-127
        if (bx >= 96) {
            int u = bx - 96, ntile = u >> 3, ks = u & 7;
            gemm2<2>(h2last, g_ctx, nullptr, 0,
                     Wcdn, 1024, 1 << 30, nullptr, 0,
                     ntile * 128, 1 << 30, ks * 128, ks * 128 + 128,
                     g_cdp + (long)ks * 32768, 512, nullptr, nullptr, 0, sh);
        }
        gsync(gs);
        // E2: cdn_reduce(299) + logits_reduce(298)
        {
            int gid = bx * NTHR + tid;
            if (gid >= 32768) {
                int idx = gid - 32768;
                float s = bcdn[idx & 511];
#pragma unroll
                for (int ks = 0; ks < 8; ks++) s += g_cdp[ks * 32768 + idx];
                g_cdn[idx] = fmaxf(s, 0.f);
            }
            for (int e = gid; e < Bsz * Vsz; e += GRID * NTHR) {
                int m = e / Vsz, n = e - m * Vsz;
                out[((long)m * Tsz + (Tsz - 2)) * Vsz + n] =
                    g_lgp[0][m * 5120 + n] + g_lgp[1][m * 5120 + n] + bcls[n];
            }
        }
        gsync(gs);
        // E3: logits(299), both k-halves
        if (bx < 40) {
            gemm2<0>(g_cdn, nullptr, nullptr, 512,
                     emb, 512, 1 << 30, nullptr, 0,
                     bx * 128, Vsz, 0, 256,
                     g_lgp[0], 5120, nullptr, nullptr, 0, sh);
        } else if (bx < 80) {
            int tile = bx - 40;
            gemm2<0>(g_cdn, nullptr, nullptr, 512,
                     emb, 512, 1 << 30, nullptr, 0,
                     tile * 128, Vsz, 256, 512,
                     g_lgp[1], 5120, nullptr, nullptr, 0, sh);
        }
        gsync(gs);
        // E4: logits_reduce(299)
        {
            int gid = bx * NTHR + tid;
            for (int e = gid; e < Bsz * Vsz; e += GRID * NTHR) {
                int m = e / Vsz, n = e - m * Vsz;
                out[((long)m * Tsz + (Tsz - 1)) * Vsz + n] =
                    g_lgp[0][m * 5120 + n] + g_lgp[1][m * 5120 + n] + bcls[n];
            }
        }
    }
}

extern "C" void kernel_launch(void* const* d_in, const int* in_sizes, int n_in,
                              void* d_out, int out_size) {
    mega<<<GRID, NTHR>>>(
        (const float*)d_in[0],  (const int*)d_in[1],   (const float*)d_in[2],
        (const float*)d_in[3],  (const float*)d_in[4],
        (const float*)d_in[5],  (const float*)d_in[6],
        (const float*)d_in[7],  (const float*)d_in[8],
        (const float*)d_in[9],  (const float*)d_in[10],
        (const float*)d_in[11], (const float*)d_in[12],
        (const float*)d_in[13], (const float*)d_in[14],
        (const float*)d_in[15], (const float*)d_in[16],
        (const float*)d_in[17], (const float*)d_in[18],
        (const float*)d_in[19], (float*)d_out);
}

// round 9
// speedup vs baseline: 1.5397x; 1.2148x over previous
#include <cuda_runtime.h>

#define GRID 148
#define NTHR 512
#define Bsz 64
#define Ssz 1024
#define Tsz 300
#define Hsz 512
#define Vsz 5000
#define KQn 256

typedef unsigned long long ull;

// ---------------- device scratch ----------------
__device__ float g_k[Bsz * Ssz * KQn];
__device__ float g_v[Bsz * Ssz * Hsz];
__device__ float g_h1[2][Bsz * Hsz];
__device__ float g_c1[Bsz * Hsz];
__device__ float g_h2[2][Bsz * Hsz];
__device__ float g_c2[Bsz * Hsz];
__device__ float g_ctx[Bsz * Hsz];
__device__ float g_cdn[Bsz * Hsz];
__device__ float g_g1p[8 * Bsz * 2048];
__device__ float g_g2p[9 * Bsz * 2048];
__device__ float g_cdp[5 * Bsz * 512];
__device__ float g_lgp[2][Bsz * 5120];
__device__ volatile int g_flags[GRID];
__device__ volatile int g_genv;

// ---------------- shared arena ----------------
struct __align__(16) Sh {
    union {
        struct { float As[64][36]; float Bs[128][36]; } g;
        struct { float h2s[512]; float qs[256]; float sc[1024]; float red[16]; } a;
    } u;
    int toks[64];
};

// ---------------- grid barrier ----------------
__device__ __forceinline__ void gsync(int& gs) {
    gs++;
    __syncthreads();
    if (blockIdx.x == 0) {
        if (threadIdx.x > 0 && threadIdx.x < GRID)
            while (g_flags[threadIdx.x] < gs) __nanosleep(32);
        __syncthreads();
        if (threadIdx.x == 0) { __threadfence(); g_genv = gs; }
    } else if (threadIdx.x == 0) {
        __threadfence();
        g_flags[blockIdx.x] = gs;
        while (g_genv < gs) __nanosleep(32);
    }
    __syncthreads();
    __threadfence();
}

__device__ __forceinline__ float sigf(float x) { return 1.f / (1.f + __expf(-x)); }

__device__ __forceinline__ void fma2(ull& d, ull a, ull b) {
    asm("fma.rn.f32x2 %0, %1, %2, %3;" : "=l"(d) : "l"(a), "l"(b), "l"(d));
}
__device__ __forceinline__ float pairsum(ull x) {
    float lo, hi;
    asm("mov.b64 {%0, %1}, %2;" : "=f"(lo), "=f"(hi) : "l"(x));
    return lo + hi;
}

// ---------------- 64M x 128N GEMM tile, f32x2, register-prefetched ---------
// out[m][n] = sum_k A[m][k] * B[n][k]
// AM 0: A row-major stride arow. AM 1: [emb[tok]|A1|A2] each 512.
// AM 2: [A0(512)|A1(512+)]. B row n: k<segB -> B0(len L0) else B1(len L1).
template <int AM>
__device__ __forceinline__ void gemm2(
    const float* __restrict__ A0, const float* __restrict__ A1,
    const float* __restrict__ A2, long arow,
    const float* __restrict__ B0, long L0, int segB,
    const float* __restrict__ B1, long L1,
    int nbase, int Nmax, int kbeg, int kend,
    float* __restrict__ outp, long OS, const float* __restrict__ bias,
    const int* __restrict__ yy, int t, Sh& sh)
{
    const int tid = threadIdx.x;
    const int nt = tid & 31;
    const int mt = tid >> 5;
    const int ar = tid >> 3;
    const int kq4 = (tid & 7) * 4;

    if (AM == 1) {
        if (tid < 64) sh.toks[tid] = (t == 0) ? 0 : yy[tid * Tsz + (t - 1)];
        __syncthreads();
    }

    ull acc[4][4];
#pragma unroll
    for (int i = 0; i < 4; i++)
#pragma unroll
        for (int j = 0; j < 4; j++) acc[i][j] = 0ULL;

    float4 pa, pb0, pb1;
    auto loadA = [&](int kb, float4& d) {
        int k = kb + kq4;
        const float* rp;
        if (AM == 0)      rp = A0 + (long)ar * arow + k;
        else if (AM == 1) rp = (k < 512)  ? A0 + (long)sh.toks[ar] * 512 + k
                         : (k < 1024) ? A1 + ar * 512 + (k - 512)
                                      : A2 + ar * 512 + (k - 1024);
        else              rp = (k < 512) ? A0 + ar * 512 + k
                                         : A1 + ar * 512 + (k - 512);
        d = *(const float4*)rp;
    };
    auto loadB = [&](int kb, int n, float4& d) {
        int ng = nbase + n;
        int k = kb + kq4;
        d = make_float4(0.f, 0.f, 0.f, 0.f);
        if (ng < Nmax) {
            const float* rp = (k < segB) ? B0 + (long)ng * L0 + k
                                         : B1 + (long)ng * L1 + (k - segB);
            d = *(const float4*)rp;
        }
    };

    loadA(kbeg, pa);
    loadB(kbeg, ar, pb0);
    loadB(kbeg, ar + 64, pb1);

    for (int kb = kbeg; kb < kend; kb += 32) {
        __syncthreads();
        *(float4*)&sh.u.g.As[ar][kq4]      = pa;
        *(float4*)&sh.u.g.Bs[ar][kq4]      = pb0;
        *(float4*)&sh.u.g.Bs[ar + 64][kq4] = pb1;
        __syncthreads();
        if (kb + 32 < kend) {
            loadA(kb + 32, pa);
            loadB(kb + 32, ar, pb0);
            loadB(kb + 32, ar + 64, pb1);
        }
#pragma unroll
        for (int kq = 0; kq < 8; kq++) {
            ull a0[4], a1[4], b0[4], b1[4];
#pragma unroll
            for (int j = 0; j < 4; j++) {
                ulonglong2 tb = *(const ulonglong2*)&sh.u.g.Bs[nt + 32 * j][4 * kq];
                b0[j] = tb.x; b1[j] = tb.y;
            }
#pragma unroll
            for (int i = 0; i < 4; i++) {
                ulonglong2 ta = *(const ulonglong2*)&sh.u.g.As[mt * 4 + i][4 * kq];
                a0[i] = ta.x; a1[i] = ta.y;
            }
#pragma unroll
            for (int i = 0; i < 4; i++)
#pragma unroll
                for (int j = 0; j < 4; j++) {
                    fma2(acc[i][j], a0[i], b0[j]);
                    fma2(acc[i][j], a1[i], b1[j]);
                }
        }
    }
    __syncthreads();

#pragma unroll
    for (int i = 0; i < 4; i++) {
        long m = mt * 4 + i;
#pragma unroll
        for (int j = 0; j < 4; j++) {
            int n = nbase + nt + 32 * j;
            if (n < Nmax) {
                float s = pairsum(acc[i][j]);
                if (bias) s += bias[n];
                outp[m * OS + n] = s;
            }
        }
    }
    __syncthreads();
}

// ---------------- persistent mega-kernel ----------------
__global__ void __launch_bounds__(NTHR, 1)
mega(const float* __restrict__ enc, const int* __restrict__ y,
     const float* __restrict__ emb,
     const float* __restrict__ Wq, const float* __restrict__ bq,
     const float* __restrict__ Wk, const float* __restrict__ bk,
     const float* __restrict__ Wv, const float* __restrict__ bv,
     const float* __restrict__ Wih1, const float* __restrict__ bih1,
     const float* __restrict__ Whh1, const float* __restrict__ bhh1,
     const float* __restrict__ Wih2, const float* __restrict__ bih2,
     const float* __restrict__ Whh2, const float* __restrict__ bhh2,
     const float* __restrict__ Wcdn, const float* __restrict__ bcdn,
     const float* __restrict__ bcls, float* __restrict__ out)
{
    __shared__ Sh sh;
    const int tid = threadIdx.x;
    const int bx = blockIdx.x;
    int gs = g_genv;

    // ---- init: zero recurrent state (5 arrays) ----
    for (int i = bx * NTHR + tid; i < 5 * Bsz * Hsz; i += GRID * NTHR) {
        int a = i >> 15, j = i & 32767;
        float* p = a == 0 ? g_h1[0] : a == 1 ? g_c1 : a == 2 ? g_h2[0]
                 : a == 3 ? g_c2 : g_ctx;
        p[j] = 0.f;
    }
    // ---- kv projection ----
    for (int j = bx; j < 6144; j += GRID) {
        if (j < 2048) {
            int mt_ = j >> 1, nt_ = j & 1;
            gemm2<0>(enc + (long)mt_ * 64 * 512, nullptr, nullptr, 512,
                     Wk, 512, 1 << 30, nullptr, 0,
                     nt_ * 128, 1 << 30, 0, 512,
                     g_k + (long)mt_ * 64 * KQn, KQn, bk, nullptr, 0, sh);
        } else {
            int v = j - 2048;
            int mt_ = v >> 2, nt_ = v & 3;
            gemm2<0>(enc + (long)mt_ * 64 * 512, nullptr, nullptr, 512,
                     Wv, 512, 1 << 30, nullptr, 0,
                     nt_ * 128, 1 << 30, 0, 512,
                     g_v + (long)mt_ * 64 * Hsz, Hsz, bv, nullptr, 0, sh);
        }
    }
    gsync(gs);

    for (int t = 0; t < Tsz; t++) {
        const float* h1o = g_h1[t & 1];
        float*       h1n = g_h1[(t + 1) & 1];
        const float* h2o = g_h2[t & 1];
        float*       h2n = g_h2[(t + 1) & 1];

        // ---- P1: LSTM1 (blk 0-127: 16nt x 8sk, k=192) || cdn(t-1) (128-147) ----
        if (bx < 128) {
            int ntile = bx >> 3, ks = bx & 7;
            gemm2<1>(emb, g_ctx, h1o, 0,
                     Wih1, 1024, 1024, Whh1, 512,
                     ntile * 128, 1 << 30, ks * 192, ks * 192 + 192,
                     g_g1p + (long)ks * 131072, 2048, nullptr, y, t, sh);
        } else if (t > 0) {
            int u = bx - 128, ntile = u / 5, ks = u % 5;   // 4nt x 5sk uneven k
            int kb = ks < 2 ? ks * 224 : 448 + (ks - 2) * 192;
            int kl = ks < 2 ? 224 : 192;
            gemm2<2>(h2o, g_ctx, nullptr, 0,
                     Wcdn, 1024, 1 << 30, nullptr, 0,
                     ntile * 128, 1 << 30, kb, kb + kl,
                     g_cdp + (long)ks * 32768, 512, nullptr, nullptr, 0, sh);
        }
        gsync(gs);

        // ---- P2: cell1 + cdn-red(t-1) + logits-red(t-2) ----
        {
            int gid = bx * NTHR + tid;
            if (gid < 32768) {
                int b = gid >> 9, u = gid & 511;
                float gt[4];
#pragma unroll
                for (int g = 0; g < 4; g++) {
                    int n = g * 512 + u;
                    float s = bih1[n] + bhh1[n];
#pragma unroll
                    for (int ks = 0; ks < 8; ks++)
                        s += g_g1p[ks * 131072 + b * 2048 + n];
                    gt[g] = s;
                }
                float cn = sigf(gt[1]) * g_c1[gid] + sigf(gt[0]) * tanhf(gt[2]);
                g_c1[gid] = cn;
                h1n[gid] = sigf(gt[3]) * tanhf(cn);
            } else if (t > 0 && gid < 65536) {
                int idx = gid - 32768;
                float s = bcdn[idx & 511];
#pragma unroll
                for (int ks = 0; ks < 5; ks++) s += g_cdp[ks * 32768 + idx];
                g_cdn[idx] = fmaxf(s, 0.f);
            }
            if (t > 1) {
                for (int e = gid; e < Bsz * Vsz; e += GRID * NTHR) {
                    int m = e / Vsz, n = e - m * Vsz;
                    out[((long)m * Tsz + (t - 2)) * Vsz + n] =
                        g_lgp[0][m * 5120 + n] + g_lgp[1][m * 5120 + n] + bcls[n];
                }
            }
            gsync(gs);
        }

        // ---- P3: LSTM2 (blk 0-143: 16nt x 9sk, uneven k) ----
        if (bx < 144) {
            int ntile = bx / 9, ks = bx % 9;
            int kb = ks < 5 ? ks * 128 : 640 + (ks - 5) * 96;
            int kl = ks < 5 ? 128 : 96;
            gemm2<2>(h1n, h2o, nullptr, 0,
                     Wih2, 512, 512, Whh2, 512,
                     ntile * 128, 1 << 30, kb, kb + kl,
                     g_g2p + (long)ks * 131072, 2048, nullptr, nullptr, 0, sh);
        }
        gsync(gs);

        // ---- P4: attention (blk 0-63, fully block-local) || logits(t-1) (64-143) ----
        if (bx < 64) {
            int b = bx, lane = tid & 31, w = tid >> 5;
            // cell2: one unit per thread (512 units)
            {
                int u = tid;
                float gt[4];
#pragma unroll
                for (int g = 0; g < 4; g++) {
                    int n = g * 512 + u;
                    float s = bih2[n] + bhh2[n];
#pragma unroll
                    for (int ks = 0; ks < 9; ks++)
                        s += g_g2p[ks * 131072 + b * 2048 + n];
                    gt[g] = s;
                }
                float cn = sigf(gt[1]) * g_c2[b * 512 + u] + sigf(gt[0]) * tanhf(gt[2]);
                float h = sigf(gt[3]) * tanhf(cn);
                g_c2[b * 512 + u] = cn;
                h2n[b * 512 + u] = h;
                sh.u.a.h2s[u] = h;
            }
            __syncthreads();
            // q projection: 16 warps x 16 outputs (scale folded)
            {
                const float4* h24 = (const float4*)sh.u.a.h2s;
                float4 hv0 = h24[lane], hv1 = h24[32 + lane],
                       hv2 = h24[64 + lane], hv3 = h24[96 + lane];
#pragma unroll 2
                for (int jj = 0; jj < 16; jj++) {
                    int j = w * 16 + jj;
                    const float4* wr = (const float4*)(Wq + (long)j * 512);
                    float4 w0 = wr[lane], w1 = wr[32 + lane],
                           w2 = wr[64 + lane], w3 = wr[96 + lane];
                    float s = hv0.x * w0.x + hv0.y * w0.y + hv0.z * w0.z + hv0.w * w0.w
                            + hv1.x * w1.x + hv1.y * w1.y + hv1.z * w1.z + hv1.w * w1.w
                            + hv2.x * w2.x + hv2.y * w2.y + hv2.z * w2.z + hv2.w * w2.w
                            + hv3.x * w3.x + hv3.y * w3.y + hv3.z * w3.z + hv3.w * w3.w;
#pragma unroll
                    for (int o = 16; o; o >>= 1) s += __shfl_xor_sync(~0u, s, o);
                    if (lane == 0) sh.u.a.qs[j] = (s + bq[j]) * 0.0625f;
                }
            }
            __syncthreads();
            // scores: 16 warps x 64 rows -> smem
            {
                const float4* q4 = (const float4*)sh.u.a.qs;
                float4 qr0 = q4[lane], qr1 = q4[32 + lane];
                int rbase = w * 64;
#pragma unroll 4
                for (int i = 0; i < 64; i++) {
                    int row = rbase + i;
                    const float4* kr = (const float4*)(g_k + ((long)b * 1024 + row) * 256);
                    float4 k0 = kr[lane], k1 = kr[32 + lane];
                    float a = qr0.x * k0.x + qr0.y * k0.y + qr0.z * k0.z + qr0.w * k0.w
                            + qr1.x * k1.x + qr1.y * k1.y + qr1.z * k1.z + qr1.w * k1.w;
#pragma unroll
                    for (int o = 16; o; o >>= 1) a += __shfl_xor_sync(~0u, a, o);
                    if (lane == 0) sh.u.a.sc[row] = a;
                }
            }
            __syncthreads();
            // softmax (block-local)
            float inv;
            {
                float* sc = sh.u.a.sc;
                float* red = sh.u.a.red;
                float mx = fmaxf(sc[tid], sc[tid + 512]);
#pragma unroll
                for (int o = 16; o; o >>= 1) mx = fmaxf(mx, __shfl_xor_sync(~0u, mx, o));
                if (lane == 0) red[w] = mx;
                __syncthreads();
                mx = red[0];
#pragma unroll
                for (int i = 1; i < 16; i++) mx = fmaxf(mx, red[i]);
                __syncthreads();
                float e0 = __expf(sc[tid] - mx);
                float e1 = __expf(sc[tid + 512] - mx);
                sc[tid] = e0; sc[tid + 512] = e1;
                float ls = e0 + e1;
#pragma unroll
                for (int o = 16; o; o >>= 1) ls += __shfl_xor_sync(~0u, ls, o);
                if (lane == 0) red[w] = ls;
                __syncthreads();
                float tot = 0.f;
#pragma unroll
                for (int i = 0; i < 16; i++) tot += red[i];
                inv = 1.f / tot;
            }
            // context: one column per thread, full S
            {
                const float* sc = sh.u.a.sc;
                const float* vp = g_v + (long)b * (Ssz * Hsz) + tid;
                float a0 = 0.f, a1 = 0.f, a2 = 0.f, a3 = 0.f;
                float a4 = 0.f, a5 = 0.f, a6 = 0.f, a7 = 0.f;
#pragma unroll 4
                for (int s2 = 0; s2 < 1024; s2 += 8) {
                    a0 += sc[s2]     * vp[(long)(s2)     * 512];
                    a1 += sc[s2 + 1] * vp[(long)(s2 + 1) * 512];
                    a2 += sc[s2 + 2] * vp[(long)(s2 + 2) * 512];
                    a3 += sc[s2 + 3] * vp[(long)(s2 + 3) * 512];
                    a4 += sc[s2 + 4] * vp[(long)(s2 + 4) * 512];
                    a5 += sc[s2 + 5] * vp[(long)(s2 + 5) * 512];
                    a6 += sc[s2 + 6] * vp[(long)(s2 + 6) * 512];
                    a7 += sc[s2 + 7] * vp[(long)(s2 + 7) * 512];
                }
                g_ctx[b * 512 + tid] =
                    (((a0 + a1) + (a2 + a3)) + ((a4 + a5) + (a6 + a7))) * inv;
            }
        } else if (t > 0 && bx < 144) {
            int u = bx - 64, tile = u >> 1, kh = u & 1;   // 40nt x 2sk, k=256
            gemm2<0>(g_cdn, nullptr, nullptr, 512,
                     emb, 512, 1 << 30, nullptr, 0,
                     tile * 128, Vsz, kh * 256, kh * 256 + 256,
                     g_lgp[kh], 5120, nullptr, nullptr, 0, sh);
        }
        gsync(gs);
    }

    // ---- epilogue ----
    {
        const float* h2last = g_h2[Tsz & 1];
        // E1: logits-red(Tsz-2) on blk<128 || cdn(Tsz-1) partials on blk 128-147
        if (bx >= 128) {
            int u = bx - 128, ntile = u / 5, ks = u % 5;
            int kb = ks < 2 ? ks * 224 : 448 + (ks - 2) * 192;
            int kl = ks < 2 ? 224 : 192;
            gemm2<2>(h2last, g_ctx, nullptr, 0,
                     Wcdn, 1024, 1 << 30, nullptr, 0,
                     ntile * 128, 1 << 30, kb, kb + kl,
                     g_cdp + (long)ks * 32768, 512, nullptr, nullptr, 0, sh);
        } else {
            int gid = bx * NTHR + tid;
            for (int e = gid; e < Bsz * Vsz; e += 128 * NTHR) {
                int m = e / Vsz, n = e - m * Vsz;
                out[((long)m * Tsz + (Tsz - 2)) * Vsz + n] =
                    g_lgp[0][m * 5120 + n] + g_lgp[1][m * 5120 + n] + bcls[n];
            }
        }
        gsync(gs);
        // E2: cdn-reduce(Tsz-1)
        {
            int gid = bx * NTHR + tid;
            if (gid < 32768) {
                float s = bcdn[gid & 511];
#pragma unroll
                for (int ks = 0; ks < 5; ks++) s += g_cdp[ks * 32768 + gid];
                g_cdn[gid] = fmaxf(s, 0.f);
            }
        }
        gsync(gs);
        // E3: logits(Tsz-1) partials on 80 blocks
        if (bx < 80) {
            int tile = bx >> 1, kh = bx & 1;
            gemm2<0>(g_cdn, nullptr, nullptr, 512,
                     emb, 512, 1 << 30, nullptr, 0,
                     tile * 128, Vsz, kh * 256, kh * 256 + 256,
                     g_lgp[kh], 5120, nullptr, nullptr, 0, sh);
        }
        gsync(gs);
        // E4: logits-reduce(Tsz-1)
        {
            int gid = bx * NTHR + tid;
            for (int e = gid; e < Bsz * Vsz; e += GRID * NTHR) {
                int m = e / Vsz, n = e - m * Vsz;
                out[((long)m * Tsz + (Tsz - 1)) * Vsz + n] =
                    g_lgp[0][m * 5120 + n] + g_lgp[1][m * 5120 + n] + bcls[n];
            }
        }
    }
}

extern "C" void kernel_launch(void* const* d_in, const int* in_sizes, int n_in,
                              void* d_out, int out_size) {
    mega<<<GRID, NTHR>>>(
        (const float*)d_in[0],  (const int*)d_in[1],   (const float*)d_in[2],
        (const float*)d_in[3],  (const float*)d_in[4],
        (const float*)d_in[5],  (const float*)d_in[6],
        (const float*)d_in[7],  (const float*)d_in[8],
        (const float*)d_in[9],  (const float*)d_in[10],
        (const float*)d_in[11], (const float*)d_in[12],
        (const float*)d_in[13], (const float*)d_in[14],
        (const float*)d_in[15], (const float*)d_in[16],
        (const float*)d_in[17], (const float*)d_in[18],
        (const float*)d_in[19], (float*)d_out);
}

// round 10
// speedup vs baseline: 1.8087x; 1.1747x over previous
#include <cuda_runtime.h>
#include <cuda_bf16.h>

#define GRID 148
#define NTHR 512
#define Bsz 64
#define Ssz 1024
#define Tsz 300
#define Hsz 512
#define Vsz 5000
#define KQn 256

typedef unsigned long long ull;

// ---------------- device scratch ----------------
__device__ __nv_bfloat16 g_k[Bsz * Ssz * KQn];   // bf16 keys   (32 MB)
__device__ __nv_bfloat16 g_v[Bsz * Ssz * Hsz];   // bf16 values (64 MB)
__device__ float g_h1[2][Bsz * Hsz];
__device__ float g_c1[Bsz * Hsz];
__device__ float g_h2[2][Bsz * Hsz];
__device__ float g_c2[Bsz * Hsz];
__device__ float g_ctx[Bsz * Hsz];
__device__ float g_cdn[Bsz * Hsz];
__device__ float g_g1p[8 * Bsz * 2048];
__device__ float g_g2p[9 * Bsz * 2048];
__device__ float g_cdp[5 * Bsz * 512];
__device__ float g_lgp[2][Bsz * 5120];
__device__ volatile int g_flags[GRID];
__device__ volatile int g_genv;

// ---------------- shared arena ----------------
struct __align__(16) Sh {
    union {
        struct { float As[64][36]; float Bs[128][36]; } g;
        struct { float h2s[512]; float qs[256]; float sc[1024];
                 float red[16]; float part[8][528]; } a;
    } u;
    int toks[64];
};

// ---------------- grid barrier ----------------
__device__ __forceinline__ void gsync(int& gs) {
    gs++;
    __syncthreads();
    if (blockIdx.x == 0) {
        if (threadIdx.x > 0 && threadIdx.x < GRID)
            while (g_flags[threadIdx.x] < gs) __nanosleep(32);
        __syncthreads();
        if (threadIdx.x == 0) { __threadfence(); g_genv = gs; }
    } else if (threadIdx.x == 0) {
        __threadfence();
        g_flags[blockIdx.x] = gs;
        while (g_genv < gs) __nanosleep(32);
    }
    __syncthreads();
    __threadfence();
}

__device__ __forceinline__ float sigf(float x) { return 1.f / (1.f + __expf(-x)); }

__device__ __forceinline__ void fma2(ull& d, ull a, ull b) {
    asm("fma.rn.f32x2 %0, %1, %2, %3;" : "=l"(d) : "l"(a), "l"(b), "l"(d));
}
__device__ __forceinline__ float pairsum(ull x) {
    float lo, hi;
    asm("mov.b64 {%0, %1}, %2;" : "=f"(lo), "=f"(hi) : "l"(x));
    return lo + hi;
}
// bf16x2 (packed in u32) -> two fp32 via shifts
__device__ __forceinline__ float2 bf2f(unsigned p) {
    float2 r;
    r.x = __uint_as_float(p << 16);
    r.y = __uint_as_float(p & 0xffff0000u);
    return r;
}

// ---------------- 64M x 128N GEMM tile, f32x2, register-prefetched ---------
// out[m][n] = sum_k A[m][k] * B[n][k]
// AM 0: A row-major stride arow. AM 1: [emb[tok]|A1|A2] each 512.
// AM 2: [A0(512)|A1(512+)]. B row n: k<segB -> B0(len L0) else B1(len L1).
// OB 1: output cast to bf16 (outp reinterpreted).
template <int AM, int OB>
__device__ __forceinline__ void gemm2(
    const float* __restrict__ A0, const float* __restrict__ A1,
    const float* __restrict__ A2, long arow,
    const float* __restrict__ B0, long L0, int segB,
    const float* __restrict__ B1, long L1,
    int nbase, int Nmax, int kbeg, int kend,
    void* __restrict__ outp, long OS, const float* __restrict__ bias,
    const int* __restrict__ yy, int t, Sh& sh)
{
    const int tid = threadIdx.x;
    const int nt = tid & 31;
    const int mt = tid >> 5;
    const int ar = tid >> 3;
    const int kq4 = (tid & 7) * 4;

    if (AM == 1) {
        if (tid < 64) sh.toks[tid] = (t == 0) ? 0 : yy[tid * Tsz + (t - 1)];
        __syncthreads();
    }

    ull acc[4][4];
#pragma unroll
    for (int i = 0; i < 4; i++)
#pragma unroll
        for (int j = 0; j < 4; j++) acc[i][j] = 0ULL;

    float4 pa, pb0, pb1;
    auto loadA = [&](int kb, float4& d) {
        int k = kb + kq4;
        const float* rp;
        if (AM == 0)      rp = A0 + (long)ar * arow + k;
        else if (AM == 1) rp = (k < 512)  ? A0 + (long)sh.toks[ar] * 512 + k
                         : (k < 1024) ? A1 + ar * 512 + (k - 512)
                                      : A2 + ar * 512 + (k - 1024);
        else              rp = (k < 512) ? A0 + ar * 512 + k
                                         : A1 + ar * 512 + (k - 512);
        d = *(const float4*)rp;
    };
    auto loadB = [&](int kb, int n, float4& d) {
        int ng = nbase + n;
        int k = kb + kq4;
        d = make_float4(0.f, 0.f, 0.f, 0.f);
        if (ng < Nmax) {
            const float* rp = (k < segB) ? B0 + (long)ng * L0 + k
                                         : B1 + (long)ng * L1 + (k - segB);
            d = *(const float4*)rp;
        }
    };

    loadA(kbeg, pa);
    loadB(kbeg, ar, pb0);
    loadB(kbeg, ar + 64, pb1);

    for (int kb = kbeg; kb < kend; kb += 32) {
        __syncthreads();
        *(float4*)&sh.u.g.As[ar][kq4]      = pa;
        *(float4*)&sh.u.g.Bs[ar][kq4]      = pb0;
        *(float4*)&sh.u.g.Bs[ar + 64][kq4] = pb1;
        __syncthreads();
        if (kb + 32 < kend) {
            loadA(kb + 32, pa);
            loadB(kb + 32, ar, pb0);
            loadB(kb + 32, ar + 64, pb1);
        }
#pragma unroll
        for (int kq = 0; kq < 8; kq++) {
            ull a0[4], a1[4], b0[4], b1[4];
#pragma unroll
            for (int j = 0; j < 4; j++) {
                ulonglong2 tb = *(const ulonglong2*)&sh.u.g.Bs[nt + 32 * j][4 * kq];
                b0[j] = tb.x; b1[j] = tb.y;
            }
#pragma unroll
            for (int i = 0; i < 4; i++) {
                ulonglong2 ta = *(const ulonglong2*)&sh.u.g.As[mt * 4 + i][4 * kq];
                a0[i] = ta.x; a1[i] = ta.y;
            }
#pragma unroll
            for (int i = 0; i < 4; i++)
#pragma unroll
                for (int j = 0; j < 4; j++) {
                    fma2(acc[i][j], a0[i], b0[j]);
                    fma2(acc[i][j], a1[i], b1[j]);
                }
        }
    }
    __syncthreads();

#pragma unroll
    for (int i = 0; i < 4; i++) {
        long m = mt * 4 + i;
#pragma unroll
        for (int j = 0; j < 4; j++) {
            int n = nbase + nt + 32 * j;
            if (n < Nmax) {
                float s = pairsum(acc[i][j]);
                if (bias) s += bias[n];
                if (OB) ((__nv_bfloat16*)outp)[m * OS + n] = __float2bfloat16(s);
                else    ((float*)outp)[m * OS + n] = s;
            }
        }
    }
    __syncthreads();
}

// ---------------- persistent mega-kernel ----------------
__global__ void __launch_bounds__(NTHR, 1)
mega(const float* __restrict__ enc, const int* __restrict__ y,
     const float* __restrict__ emb,
     const float* __restrict__ Wq, const float* __restrict__ bq,
     const float* __restrict__ Wk, const float* __restrict__ bk,
     const float* __restrict__ Wv, const float* __restrict__ bv,
     const float* __restrict__ Wih1, const float* __restrict__ bih1,
     const float* __restrict__ Whh1, const float* __restrict__ bhh1,
     const float* __restrict__ Wih2, const float* __restrict__ bih2,
     const float* __restrict__ Whh2, const float* __restrict__ bhh2,
     const float* __restrict__ Wcdn, const float* __restrict__ bcdn,
     const float* __restrict__ bcls, float* __restrict__ out)
{
    __shared__ Sh sh;
    const int tid = threadIdx.x;
    const int bx = blockIdx.x;
    int gs = g_genv;

    // ---- init: zero recurrent state ----
    for (int i = bx * NTHR + tid; i < 5 * Bsz * Hsz; i += GRID * NTHR) {
        int a = i >> 15, j = i & 32767;
        float* p = a == 0 ? g_h1[0] : a == 1 ? g_c1 : a == 2 ? g_h2[0]
                 : a == 3 ? g_c2 : g_ctx;
        p[j] = 0.f;
    }
    // ---- kv projection (bf16 output) ----
    for (int j = bx; j < 6144; j += GRID) {
        if (j < 2048) {
            int mt_ = j >> 1, nt_ = j & 1;
            gemm2<0, 1>(enc + (long)mt_ * 64 * 512, nullptr, nullptr, 512,
                        Wk, 512, 1 << 30, nullptr, 0,
                        nt_ * 128, 1 << 30, 0, 512,
                        g_k + (long)mt_ * 64 * KQn, KQn, bk, nullptr, 0, sh);
        } else {
            int v = j - 2048;
            int mt_ = v >> 2, nt_ = v & 3;
            gemm2<0, 1>(enc + (long)mt_ * 64 * 512, nullptr, nullptr, 512,
                        Wv, 512, 1 << 30, nullptr, 0,
                        nt_ * 128, 1 << 30, 0, 512,
                        g_v + (long)mt_ * 64 * Hsz, Hsz, bv, nullptr, 0, sh);
        }
    }
    gsync(gs);

    for (int t = 0; t < Tsz; t++) {
        const float* h1o = g_h1[t & 1];
        float*       h1n = g_h1[(t + 1) & 1];
        const float* h2o = g_h2[t & 1];
        float*       h2n = g_h2[(t + 1) & 1];

        // ---- P1: LSTM1 (blk 0-127) || cdn(t-1) (128-147) ----
        if (bx < 128) {
            int ntile = bx >> 3, ks = bx & 7;
            gemm2<1, 0>(emb, g_ctx, h1o, 0,
                        Wih1, 1024, 1024, Whh1, 512,
                        ntile * 128, 1 << 30, ks * 192, ks * 192 + 192,
                        g_g1p + (long)ks * 131072, 2048, nullptr, y, t, sh);
        } else if (t > 0) {
            int u = bx - 128, ntile = u / 5, ks = u % 5;
            int kb = ks < 2 ? ks * 224 : 448 + (ks - 2) * 192;
            int kl = ks < 2 ? 224 : 192;
            gemm2<2, 0>(h2o, g_ctx, nullptr, 0,
                        Wcdn, 1024, 1 << 30, nullptr, 0,
                        ntile * 128, 1 << 30, kb, kb + kl,
                        g_cdp + (long)ks * 32768, 512, nullptr, nullptr, 0, sh);
        }
        gsync(gs);

        // ---- P2: cell1 + cdn-red(t-1) + logits-red(t-2) ----
        {
            int gid = bx * NTHR + tid;
            if (gid < 32768) {
                int b = gid >> 9, u = gid & 511;
                float gt[4];
#pragma unroll
                for (int g = 0; g < 4; g++) {
                    int n = g * 512 + u;
                    float s = bih1[n] + bhh1[n];
#pragma unroll
                    for (int ks = 0; ks < 8; ks++)
                        s += g_g1p[ks * 131072 + b * 2048 + n];
                    gt[g] = s;
                }
                float cn = sigf(gt[1]) * g_c1[gid] + sigf(gt[0]) * tanhf(gt[2]);
                g_c1[gid] = cn;
                h1n[gid] = sigf(gt[3]) * tanhf(cn);
            } else if (t > 0 && gid < 65536) {
                int idx = gid - 32768;
                float s = bcdn[idx & 511];
#pragma unroll
                for (int ks = 0; ks < 5; ks++) s += g_cdp[ks * 32768 + idx];
                g_cdn[idx] = fmaxf(s, 0.f);
            }
            if (t > 1) {
                for (int e = gid; e < Bsz * Vsz; e += GRID * NTHR) {
                    int m = e / Vsz, n = e - m * Vsz;
                    out[((long)m * Tsz + (t - 2)) * Vsz + n] =
                        g_lgp[0][m * 5120 + n] + g_lgp[1][m * 5120 + n] + bcls[n];
                }
            }
            gsync(gs);
        }

        // ---- P3: LSTM2 (blk 0-143: 16nt x 9sk, uneven k) ----
        if (bx < 144) {
            int ntile = bx / 9, ks = bx % 9;
            int kb = ks < 5 ? ks * 128 : 640 + (ks - 5) * 96;
            int kl = ks < 5 ? 128 : 96;
            gemm2<2, 0>(h1n, h2o, nullptr, 0,
                        Wih2, 512, 512, Whh2, 512,
                        ntile * 128, 1 << 30, kb, kb + kl,
                        g_g2p + (long)ks * 131072, 2048, nullptr, nullptr, 0, sh);
        }
        gsync(gs);

        // ---- P4: attention (blk 0-63, block-local) || logits(t-1) (64-143) ----
        if (bx < 64) {
            int b = bx, lane = tid & 31, w = tid >> 5;
            // cell2
            {
                int u = tid;
                float gt[4];
#pragma unroll
                for (int g = 0; g < 4; g++) {
                    int n = g * 512 + u;
                    float s = bih2[n] + bhh2[n];
#pragma unroll
                    for (int ks = 0; ks < 9; ks++)
                        s += g_g2p[ks * 131072 + b * 2048 + n];
                    gt[g] = s;
                }
                float cn = sigf(gt[1]) * g_c2[b * 512 + u] + sigf(gt[0]) * tanhf(gt[2]);
                float h = sigf(gt[3]) * tanhf(cn);
                g_c2[b * 512 + u] = cn;
                h2n[b * 512 + u] = h;
                sh.u.a.h2s[u] = h;
            }
            __syncthreads();
            // q projection: 16 warps x 16 outputs (scale folded)
            {
                const float4* h24 = (const float4*)sh.u.a.h2s;
                float4 hv0 = h24[lane], hv1 = h24[32 + lane],
                       hv2 = h24[64 + lane], hv3 = h24[96 + lane];
#pragma unroll 2
                for (int jj = 0; jj < 16; jj++) {
                    int j = w * 16 + jj;
                    const float4* wr = (const float4*)(Wq + (long)j * 512);
                    float4 w0 = wr[lane], w1 = wr[32 + lane],
                           w2 = wr[64 + lane], w3 = wr[96 + lane];
                    float s = hv0.x * w0.x + hv0.y * w0.y + hv0.z * w0.z + hv0.w * w0.w
                            + hv1.x * w1.x + hv1.y * w1.y + hv1.z * w1.z + hv1.w * w1.w
                            + hv2.x * w2.x + hv2.y * w2.y + hv2.z * w2.z + hv2.w * w2.w
                            + hv3.x * w3.x + hv3.y * w3.y + hv3.z * w3.z + hv3.w * w3.w;
#pragma unroll
                    for (int o = 16; o; o >>= 1) s += __shfl_xor_sync(~0u, s, o);
                    if (lane == 0) sh.u.a.qs[j] = (s + bq[j]) * 0.0625f;
                }
            }
            __syncthreads();
            // scores: 16 warps x 64 rows, 1 LDG.128 (8 bf16 dims) per lane per row
            {
                const float4* q4 = (const float4*)sh.u.a.qs;
                float4 qA = q4[2 * lane], qB = q4[2 * lane + 1];
                int rbase = w * 64;
#pragma unroll 4
                for (int i = 0; i < 64; i++) {
                    int row = rbase + i;
                    uint4 kv = *(const uint4*)(g_k + ((long)b * 1024 + row) * 256 + lane * 8);
                    float2 f0 = bf2f(kv.x), f1 = bf2f(kv.y),
                           f2 = bf2f(kv.z), f3 = bf2f(kv.w);
                    float a = qA.x * f0.x + qA.y * f0.y + qA.z * f1.x + qA.w * f1.y
                            + qB.x * f2.x + qB.y * f2.y + qB.z * f3.x + qB.w * f3.y;
#pragma unroll
                    for (int o = 16; o; o >>= 1) a += __shfl_xor_sync(~0u, a, o);
                    if (lane == 0) sh.u.a.sc[row] = a;
                }
            }
            __syncthreads();
            // softmax (block-local)
            float inv;
            {
                float* sc = sh.u.a.sc;
                float* red = sh.u.a.red;
                float mx = fmaxf(sc[tid], sc[tid + 512]);
#pragma unroll
                for (int o = 16; o; o >>= 1) mx = fmaxf(mx, __shfl_xor_sync(~0u, mx, o));
                if (lane == 0) red[w] = mx;
                __syncthreads();
                mx = red[0];
#pragma unroll
                for (int i = 1; i < 16; i++) mx = fmaxf(mx, red[i]);
                __syncthreads();
                float e0 = __expf(sc[tid] - mx);
                float e1 = __expf(sc[tid + 512] - mx);
                sc[tid] = e0; sc[tid + 512] = e1;
                float ls = e0 + e1;
#pragma unroll
                for (int o = 16; o; o >>= 1) ls += __shfl_xor_sync(~0u, ls, o);
                if (lane == 0) red[w] = ls;
                __syncthreads();
                float tot = 0.f;
#pragma unroll
                for (int i = 0; i < 16; i++) tot += red[i];
                inv = 1.f / tot;
            }
            // context: thread owns 8 consecutive cols (LDG.128 of bf16),
            // 8 s-strips of 128 rows, reduced via smem
            {
                const float* sc = sh.u.a.sc;
                int cg = tid & 63, sg = tid >> 6;
                const __nv_bfloat16* vbase =
                    g_v + (long)b * (Ssz * Hsz) + (long)sg * 128 * 512 + cg * 8;
                float a0 = 0.f, a1 = 0.f, a2 = 0.f, a3 = 0.f;
                float a4 = 0.f, a5 = 0.f, a6 = 0.f, a7 = 0.f;
                const float* scp = sc + sg * 128;
#pragma unroll 4
                for (int s2 = 0; s2 < 128; s2++) {
                    uint4 vv = *(const uint4*)(vbase + (long)s2 * 512);
                    float wsc = scp[s2];
                    float2 f0 = bf2f(vv.x), f1 = bf2f(vv.y),
                           f2 = bf2f(vv.z), f3 = bf2f(vv.w);
                    a0 += wsc * f0.x; a1 += wsc * f0.y;
                    a2 += wsc * f1.x; a3 += wsc * f1.y;
                    a4 += wsc * f2.x; a5 += wsc * f2.y;
                    a6 += wsc * f3.x; a7 += wsc * f3.y;
                }
                float* pp = &sh.u.a.part[sg][cg * 8];
                *(float4*)pp       = make_float4(a0, a1, a2, a3);
                *(float4*)(pp + 4) = make_float4(a4, a5, a6, a7);
                __syncthreads();
                float s = 0.f;
#pragma unroll
                for (int g = 0; g < 8; g++) s += sh.u.a.part[g][tid];
                g_ctx[b * 512 + tid] = s * inv;
            }
        } else if (t > 0 && bx < 144) {
            int u = bx - 64, tile = u >> 1, kh = u & 1;
            gemm2<0, 0>(g_cdn, nullptr, nullptr, 512,
                        emb, 512, 1 << 30, nullptr, 0,
                        tile * 128, Vsz, kh * 256, kh * 256 + 256,
                        g_lgp[kh], 5120, nullptr, nullptr, 0, sh);
        }
        gsync(gs);
    }

    // ---- epilogue ----
    {
        const float* h2last = g_h2[Tsz & 1];
        if (bx >= 128) {
            int u = bx - 128, ntile = u / 5, ks = u % 5;
            int kb = ks < 2 ? ks * 224 : 448 + (ks - 2) * 192;
            int kl = ks < 2 ? 224 : 192;
            gemm2<2, 0>(h2last, g_ctx, nullptr, 0,
                        Wcdn, 1024, 1 << 30, nullptr, 0,
                        ntile * 128, 1 << 30, kb, kb + kl,
                        g_cdp + (long)ks * 32768, 512, nullptr, nullptr, 0, sh);
        } else {
            int gid = bx * NTHR + tid;
            for (int e = gid; e < Bsz * Vsz; e += 128 * NTHR) {
                int m = e / Vsz, n = e - m * Vsz;
                out[((long)m * Tsz + (Tsz - 2)) * Vsz + n] =
                    g_lgp[0][m * 5120 + n] + g_lgp[1][m * 5120 + n] + bcls[n];
            }
        }
        gsync(gs);
        {
            int gid = bx * NTHR + tid;
            if (gid < 32768) {
                float s = bcdn[gid & 511];
#pragma unroll
                for (int ks = 0; ks < 5; ks++) s += g_cdp[ks * 32768 + gid];
                g_cdn[gid] = fmaxf(s, 0.f);
            }
        }
        gsync(gs);
        if (bx < 80) {
            int tile = bx >> 1, kh = bx & 1;
            gemm2<0, 0>(g_cdn, nullptr, nullptr, 512,
                        emb, 512, 1 << 30, nullptr, 0,
                        tile * 128, Vsz, kh * 256, kh * 256 + 256,
                        g_lgp[kh], 5120, nullptr, nullptr, 0, sh);
        }
        gsync(gs);
        {
            int gid = bx * NTHR + tid;
            for (int e = gid; e < Bsz * Vsz; e += GRID * NTHR) {
                int m = e / Vsz, n = e - m * Vsz;
                out[((long)m * Tsz + (Tsz - 1)) * Vsz + n] =
                    g_lgp[0][m * 5120 + n] + g_lgp[1][m * 5120 + n] + bcls[n];
            }
        }
    }
}

extern "C" void kernel_launch(void* const* d_in, const int* in_sizes, int n_in,
                              void* d_out, int out_size) {
    mega<<<GRID, NTHR>>>(
        (const float*)d_in[0],  (const int*)d_in[1],   (const float*)d_in[2],
        (const float*)d_in[3],  (const float*)d_in[4],
        (const float*)d_in[5],  (const float*)d_in[6],
        (const float*)d_in[7],  (const float*)d_in[8],
        (const float*)d_in[9],  (const float*)d_in[10],
        (const float*)d_in[11], (const float*)d_in[12],
        (const float*)d_in[13], (const float*)d_in[14],
        (const float*)d_in[15], (const float*)d_in[16],
        (const float*)d_in[17], (const float*)d_in[18],
        (const float*)d_in[19], (float*)d_out);
}

// round 11
// speedup vs baseline: 1.9374x; 1.0711x over previous
#include <cuda_runtime.h>
#include <cuda_fp16.h>

#define GRID 148
#define NTHR 512
#define Bsz 64
#define Ssz 1024
#define Tsz 300
#define Hsz 512
#define Vsz 5000
#define KQn 256

typedef unsigned long long ull;

// ---------------- device scratch ----------------
__device__ __half g_k[Bsz * Ssz * KQn];   // fp16 keys   (32 MB)
__device__ __half g_v[Bsz * Ssz * Hsz];   // fp16 values (64 MB)
__device__ float g_h1[2][Bsz * Hsz];
__device__ float g_c1[Bsz * Hsz];
__device__ float g_h2[2][Bsz * Hsz];
__device__ float g_c2[Bsz * Hsz];
__device__ float g_ctx[Bsz * Hsz];
__device__ float g_cdn[Bsz * Hsz];
__device__ float g_g1p[8 * Bsz * 2048];
__device__ float g_g2p[9 * Bsz * 2048];
__device__ float g_cdp[5 * Bsz * 512];
__device__ float g_lgp[2][Bsz * 5120];
__device__ volatile int g_flags[GRID];
__device__ volatile int g_genv;

// ---------------- shared arena ----------------
struct __align__(16) Sh {
    union {
        struct { float As[64][36]; float Bs[128][36]; } g;
        struct { float h2s[512]; float qs[256]; float sc[1024];
                 float red[16]; float part[8][528]; } a;
    } u;
    int toks[64];
};

// ---------------- grid barrier ----------------
__device__ __forceinline__ void gsync(int& gs) {
    gs++;
    __syncthreads();
    if (blockIdx.x == 0) {
        if (threadIdx.x > 0 && threadIdx.x < GRID)
            while (g_flags[threadIdx.x] < gs) __nanosleep(32);
        __syncthreads();
        if (threadIdx.x == 0) { __threadfence(); g_genv = gs; }
    } else if (threadIdx.x == 0) {
        __threadfence();
        g_flags[blockIdx.x] = gs;
        while (g_genv < gs) __nanosleep(32);
    }
    __syncthreads();
    __threadfence();
}

__device__ __forceinline__ float sigf(float x) { return 1.f / (1.f + __expf(-x)); }

__device__ __forceinline__ void fma2(ull& d, ull a, ull b) {
    asm("fma.rn.f32x2 %0, %1, %2, %3;" : "=l"(d) : "l"(a), "l"(b), "l"(d));
}
__device__ __forceinline__ float pairsum(ull x) {
    float lo, hi;
    asm("mov.b64 {%0, %1}, %2;" : "=f"(lo), "=f"(hi) : "l"(x));
    return lo + hi;
}
// packed half2 (in u32) -> two fp32
__device__ __forceinline__ float2 h2f(unsigned p) {
    __half2 h = *reinterpret_cast<__half2*>(&p);
    return __half22float2(h);
}

// ---------------- 64M x 128N GEMM tile, f32x2, register-prefetched ---------
// out[m][n] = sum_k A[m][k] * B[n][k]
// AM 0: A row-major stride arow. AM 1: [emb[tok]|A1|A2] each 512.
// AM 2: [A0(512)|A1(512+)]. B row n: k<segB -> B0(len L0) else B1(len L1).
// OB 1: output cast to fp16 (outp reinterpreted).
template <int AM, int OB>
__device__ __forceinline__ void gemm2(
    const float* __restrict__ A0, const float* __restrict__ A1,
    const float* __restrict__ A2, long arow,
    const float* __restrict__ B0, long L0, int segB,
    const float* __restrict__ B1, long L1,
    int nbase, int Nmax, int kbeg, int kend,
    void* __restrict__ outp, long OS, const float* __restrict__ bias,
    const int* __restrict__ yy, int t, Sh& sh)
{
    const int tid = threadIdx.x;
    const int nt = tid & 31;
    const int mt = tid >> 5;
    const int ar = tid >> 3;
    const int kq4 = (tid & 7) * 4;

    if (AM == 1) {
        if (tid < 64) sh.toks[tid] = (t == 0) ? 0 : yy[tid * Tsz + (t - 1)];
        __syncthreads();
    }

    ull acc[4][4];
#pragma unroll
    for (int i = 0; i < 4; i++)
#pragma unroll
        for (int j = 0; j < 4; j++) acc[i][j] = 0ULL;

    float4 pa, pb0, pb1;
    auto loadA = [&](int kb, float4& d) {
        int k = kb + kq4;
        const float* rp;
        if (AM == 0)      rp = A0 + (long)ar * arow + k;
        else if (AM == 1) rp = (k < 512)  ? A0 + (long)sh.toks[ar] * 512 + k
                         : (k < 1024) ? A1 + ar * 512 + (k - 512)
                                      : A2 + ar * 512 + (k - 1024);
        else              rp = (k < 512) ? A0 + ar * 512 + k
                                         : A1 + ar * 512 + (k - 512);
        d = *(const float4*)rp;
    };
    auto loadB = [&](int kb, int n, float4& d) {
        int ng = nbase + n;
        int k = kb + kq4;
        d = make_float4(0.f, 0.f, 0.f, 0.f);
        if (ng < Nmax) {
            const float* rp = (k < segB) ? B0 + (long)ng * L0 + k
                                         : B1 + (long)ng * L1 + (k - segB);
            d = *(const float4*)rp;
        }
    };

    loadA(kbeg, pa);
    loadB(kbeg, ar, pb0);
    loadB(kbeg, ar + 64, pb1);

    for (int kb = kbeg; kb < kend; kb += 32) {
        __syncthreads();
        *(float4*)&sh.u.g.As[ar][kq4]      = pa;
        *(float4*)&sh.u.g.Bs[ar][kq4]      = pb0;
        *(float4*)&sh.u.g.Bs[ar + 64][kq4] = pb1;
        __syncthreads();
        if (kb + 32 < kend) {
            loadA(kb + 32, pa);
            loadB(kb + 32, ar, pb0);
            loadB(kb + 32, ar + 64, pb1);
        }
#pragma unroll
        for (int kq = 0; kq < 8; kq++) {
            ull a0[4], a1[4], b0[4], b1[4];
#pragma unroll
            for (int j = 0; j < 4; j++) {
                ulonglong2 tb = *(const ulonglong2*)&sh.u.g.Bs[nt + 32 * j][4 * kq];
                b0[j] = tb.x; b1[j] = tb.y;
            }
#pragma unroll
            for (int i = 0; i < 4; i++) {
                ulonglong2 ta = *(const ulonglong2*)&sh.u.g.As[mt * 4 + i][4 * kq];
                a0[i] = ta.x; a1[i] = ta.y;
            }
#pragma unroll
            for (int i = 0; i < 4; i++)
#pragma unroll
                for (int j = 0; j < 4; j++) {
                    fma2(acc[i][j], a0[i], b0[j]);
                    fma2(acc[i][j], a1[i], b1[j]);
                }
        }
    }
    __syncthreads();

#pragma unroll
    for (int i = 0; i < 4; i++) {
        long m = mt * 4 + i;
#pragma unroll
        for (int j = 0; j < 4; j++) {
            int n = nbase + nt + 32 * j;
            if (n < Nmax) {
                float s = pairsum(acc[i][j]);
                if (bias) s += bias[n];
                if (OB) ((__half*)outp)[m * OS + n] = __float2half(s);
                else    ((float*)outp)[m * OS + n] = s;
            }
        }
    }
    __syncthreads();
}

// ---------------- persistent mega-kernel ----------------
__global__ void __launch_bounds__(NTHR, 1)
mega(const float* __restrict__ enc, const int* __restrict__ y,
     const float* __restrict__ emb,
     const float* __restrict__ Wq, const float* __restrict__ bq,
     const float* __restrict__ Wk, const float* __restrict__ bk,
     const float* __restrict__ Wv, const float* __restrict__ bv,
     const float* __restrict__ Wih1, const float* __restrict__ bih1,
     const float* __restrict__ Whh1, const float* __restrict__ bhh1,
     const float* __restrict__ Wih2, const float* __restrict__ bih2,
     const float* __restrict__ Whh2, const float* __restrict__ bhh2,
     const float* __restrict__ Wcdn, const float* __restrict__ bcdn,
     const float* __restrict__ bcls, float* __restrict__ out)
{
    __shared__ Sh sh;
    const int tid = threadIdx.x;
    const int bx = blockIdx.x;
    int gs = g_genv;

    // ---- init: zero recurrent state ----
    for (int i = bx * NTHR + tid; i < 5 * Bsz * Hsz; i += GRID * NTHR) {
        int a = i >> 15, j = i & 32767;
        float* p = a == 0 ? g_h1[0] : a == 1 ? g_c1 : a == 2 ? g_h2[0]
                 : a == 3 ? g_c2 : g_ctx;
        p[j] = 0.f;
    }
    // ---- kv projection (fp16 output) ----
    for (int j = bx; j < 6144; j += GRID) {
        if (j < 2048) {
            int mt_ = j >> 1, nt_ = j & 1;
            gemm2<0, 1>(enc + (long)mt_ * 64 * 512, nullptr, nullptr, 512,
                        Wk, 512, 1 << 30, nullptr, 0,
                        nt_ * 128, 1 << 30, 0, 512,
                        g_k + (long)mt_ * 64 * KQn, KQn, bk, nullptr, 0, sh);
        } else {
            int v = j - 2048;
            int mt_ = v >> 2, nt_ = v & 3;
            gemm2<0, 1>(enc + (long)mt_ * 64 * 512, nullptr, nullptr, 512,
                        Wv, 512, 1 << 30, nullptr, 0,
                        nt_ * 128, 1 << 30, 0, 512,
                        g_v + (long)mt_ * 64 * Hsz, Hsz, bv, nullptr, 0, sh);
        }
    }
    gsync(gs);

    for (int t = 0; t < Tsz; t++) {
        const float* h1o = g_h1[t & 1];
        float*       h1n = g_h1[(t + 1) & 1];
        const float* h2o = g_h2[t & 1];
        float*       h2n = g_h2[(t + 1) & 1];

        // ---- P1: LSTM1 (blk 0-127) || cdn(t-1) (128-147) ----
        if (bx < 128) {
            int ntile = bx >> 3, ks = bx & 7;
            gemm2<1, 0>(emb, g_ctx, h1o, 0,
                        Wih1, 1024, 1024, Whh1, 512,
                        ntile * 128, 1 << 30, ks * 192, ks * 192 + 192,
                        g_g1p + (long)ks * 131072, 2048, nullptr, y, t, sh);
        } else if (t > 0) {
            int u = bx - 128, ntile = u / 5, ks = u % 5;
            int kb = ks < 2 ? ks * 224 : 448 + (ks - 2) * 192;
            int kl = ks < 2 ? 224 : 192;
            gemm2<2, 0>(h2o, g_ctx, nullptr, 0,
                        Wcdn, 1024, 1 << 30, nullptr, 0,
                        ntile * 128, 1 << 30, kb, kb + kl,
                        g_cdp + (long)ks * 32768, 512, nullptr, nullptr, 0, sh);
        }
        gsync(gs);

        // ---- P2: cell1 + cdn-red(t-1) + logits-red(t-2) ----
        {
            int gid = bx * NTHR + tid;
            if (gid < 32768) {
                int b = gid >> 9, u = gid & 511;
                float gt[4];
#pragma unroll
                for (int g = 0; g < 4; g++) {
                    int n = g * 512 + u;
                    float s = bih1[n] + bhh1[n];
#pragma unroll
                    for (int ks = 0; ks < 8; ks++)
                        s += g_g1p[ks * 131072 + b * 2048 + n];
                    gt[g] = s;
                }
                float cn = sigf(gt[1]) * g_c1[gid] + sigf(gt[0]) * tanhf(gt[2]);
                g_c1[gid] = cn;
                h1n[gid] = sigf(gt[3]) * tanhf(cn);
            } else if (t > 0 && gid < 65536) {
                int idx = gid - 32768;
                float s = bcdn[idx & 511];
#pragma unroll
                for (int ks = 0; ks < 5; ks++) s += g_cdp[ks * 32768 + idx];
                g_cdn[idx] = fmaxf(s, 0.f);
            }
            if (t > 1) {
                for (int e = gid; e < Bsz * Vsz; e += GRID * NTHR) {
                    int m = e / Vsz, n = e - m * Vsz;
                    out[((long)m * Tsz + (t - 2)) * Vsz + n] =
                        g_lgp[0][m * 5120 + n] + g_lgp[1][m * 5120 + n] + bcls[n];
                }
            }
            gsync(gs);
        }

        // ---- P3: LSTM2 (blk 0-143: 16nt x 9sk, uneven k) ----
        if (bx < 144) {
            int ntile = bx / 9, ks = bx % 9;
            int kb = ks < 5 ? ks * 128 : 640 + (ks - 5) * 96;
            int kl = ks < 5 ? 128 : 96;
            gemm2<2, 0>(h1n, h2o, nullptr, 0,
                        Wih2, 512, 512, Whh2, 512,
                        ntile * 128, 1 << 30, kb, kb + kl,
                        g_g2p + (long)ks * 131072, 2048, nullptr, nullptr, 0, sh);
        }
        gsync(gs);

        // ---- P4: attention (blk 0-63, block-local) || logits(t-1) (64-143) ----
        if (bx < 64) {
            int b = bx, lane = tid & 31, w = tid >> 5;
            // cell2
            {
                int u = tid;
                float gt[4];
#pragma unroll
                for (int g = 0; g < 4; g++) {
                    int n = g * 512 + u;
                    float s = bih2[n] + bhh2[n];
#pragma unroll
                    for (int ks = 0; ks < 9; ks++)
                        s += g_g2p[ks * 131072 + b * 2048 + n];
                    gt[g] = s;
                }
                float cn = sigf(gt[1]) * g_c2[b * 512 + u] + sigf(gt[0]) * tanhf(gt[2]);
                float h = sigf(gt[3]) * tanhf(cn);
                g_c2[b * 512 + u] = cn;
                h2n[b * 512 + u] = h;
                sh.u.a.h2s[u] = h;
            }
            __syncthreads();
            // q projection: 16 warps x 16 outputs (scale folded)
            {
                const float4* h24 = (const float4*)sh.u.a.h2s;
                float4 hv0 = h24[lane], hv1 = h24[32 + lane],
                       hv2 = h24[64 + lane], hv3 = h24[96 + lane];
#pragma unroll 2
                for (int jj = 0; jj < 16; jj++) {
                    int j = w * 16 + jj;
                    const float4* wr = (const float4*)(Wq + (long)j * 512);
                    float4 w0 = wr[lane], w1 = wr[32 + lane],
                           w2 = wr[64 + lane], w3 = wr[96 + lane];
                    float s = hv0.x * w0.x + hv0.y * w0.y + hv0.z * w0.z + hv0.w * w0.w
                            + hv1.x * w1.x + hv1.y * w1.y + hv1.z * w1.z + hv1.w * w1.w
                            + hv2.x * w2.x + hv2.y * w2.y + hv2.z * w2.z + hv2.w * w2.w
                            + hv3.x * w3.x + hv3.y * w3.y + hv3.z * w3.z + hv3.w * w3.w;
#pragma unroll
                    for (int o = 16; o; o >>= 1) s += __shfl_xor_sync(~0u, s, o);
                    if (lane == 0) sh.u.a.qs[j] = (s + bq[j]) * 0.0625f;
                }
            }
            __syncthreads();
            // scores: 16 warps x 64 rows, 1 LDG.128 (8 fp16 dims) per lane per row
            {
                const float4* q4 = (const float4*)sh.u.a.qs;
                float4 qA = q4[2 * lane], qB = q4[2 * lane + 1];
                int rbase = w * 64;
#pragma unroll 4
                for (int i = 0; i < 64; i++) {
                    int row = rbase + i;
                    uint4 kv = *(const uint4*)(g_k + ((long)b * 1024 + row) * 256 + lane * 8);
                    float2 f0 = h2f(kv.x), f1 = h2f(kv.y),
                           f2 = h2f(kv.z), f3 = h2f(kv.w);
                    float a = qA.x * f0.x + qA.y * f0.y + qA.z * f1.x + qA.w * f1.y
                            + qB.x * f2.x + qB.y * f2.y + qB.z * f3.x + qB.w * f3.y;
#pragma unroll
                    for (int o = 16; o; o >>= 1) a += __shfl_xor_sync(~0u, a, o);
                    if (lane == 0) sh.u.a.sc[row] = a;
                }
            }
            __syncthreads();
            // softmax (block-local)
            float inv;
            {
                float* sc = sh.u.a.sc;
                float* red = sh.u.a.red;
                float mx = fmaxf(sc[tid], sc[tid + 512]);
#pragma unroll
                for (int o = 16; o; o >>= 1) mx = fmaxf(mx, __shfl_xor_sync(~0u, mx, o));
                if (lane == 0) red[w] = mx;
                __syncthreads();
                mx = red[0];
#pragma unroll
                for (int i = 1; i < 16; i++) mx = fmaxf(mx, red[i]);
                __syncthreads();
                float e0 = __expf(sc[tid] - mx);
                float e1 = __expf(sc[tid + 512] - mx);
                sc[tid] = e0; sc[tid + 512] = e1;
                float ls = e0 + e1;
#pragma unroll
                for (int o = 16; o; o >>= 1) ls += __shfl_xor_sync(~0u, ls, o);
                if (lane == 0) red[w] = ls;
                __syncthreads();
                float tot = 0.f;
#pragma unroll
                for (int i = 0; i < 16; i++) tot += red[i];
                inv = 1.f / tot;
            }
            // context: thread owns 8 consecutive cols (LDG.128 of fp16),
            // 8 s-strips of 128 rows, reduced via smem
            {
                const float* sc = sh.u.a.sc;
                int cg = tid & 63, sg = tid >> 6;
                const __half* vbase =
                    g_v + (long)b * (Ssz * Hsz) + (long)sg * 128 * 512 + cg * 8;
                float a0 = 0.f, a1 = 0.f, a2 = 0.f, a3 = 0.f;
                float a4 = 0.f, a5 = 0.f, a6 = 0.f, a7 = 0.f;
                const float* scp = sc + sg * 128;
#pragma unroll 8
                for (int s2 = 0; s2 < 128; s2++) {
                    uint4 vv = *(const uint4*)(vbase + (long)s2 * 512);
                    float wsc = scp[s2];
                    float2 f0 = h2f(vv.x), f1 = h2f(vv.y),
                           f2 = h2f(vv.z), f3 = h2f(vv.w);
                    a0 += wsc * f0.x; a1 += wsc * f0.y;
                    a2 += wsc * f1.x; a3 += wsc * f1.y;
                    a4 += wsc * f2.x; a5 += wsc * f2.y;
                    a6 += wsc * f3.x; a7 += wsc * f3.y;
                }
                float* pp = &sh.u.a.part[sg][cg * 8];
                *(float4*)pp       = make_float4(a0, a1, a2, a3);
                *(float4*)(pp + 4) = make_float4(a4, a5, a6, a7);
                __syncthreads();
                float s = 0.f;
#pragma unroll
                for (int g = 0; g < 8; g++) s += sh.u.a.part[g][tid];
                g_ctx[b * 512 + tid] = s * inv;
            }
        } else if (t > 0 && bx < 144) {
            int u = bx - 64, tile = u >> 1, kh = u & 1;
            gemm2<0, 0>(g_cdn, nullptr, nullptr, 512,
                        emb, 512, 1 << 30, nullptr, 0,
                        tile * 128, Vsz, kh * 256, kh * 256 + 256,
                        g_lgp[kh], 5120, nullptr, nullptr, 0, sh);
        }
        gsync(gs);
    }

    // ---- epilogue ----
    {
        const float* h2last = g_h2[Tsz & 1];
        if (bx >= 128) {
            int u = bx - 128, ntile = u / 5, ks = u % 5;
            int kb = ks < 2 ? ks * 224 : 448 + (ks - 2) * 192;
            int kl = ks < 2 ? 224 : 192;
            gemm2<2, 0>(h2last, g_ctx, nullptr, 0,
                        Wcdn, 1024, 1 << 30, nullptr, 0,
                        ntile * 128, 1 << 30, kb, kb + kl,
                        g_cdp + (long)ks * 32768, 512, nullptr, nullptr, 0, sh);
        } else {
            int gid = bx * NTHR + tid;
            for (int e = gid; e < Bsz * Vsz; e += 128 * NTHR) {
                int m = e / Vsz, n = e - m * Vsz;
                out[((long)m * Tsz + (Tsz - 2)) * Vsz + n] =
                    g_lgp[0][m * 5120 + n] + g_lgp[1][m * 5120 + n] + bcls[n];
            }
        }
        gsync(gs);
        {
            int gid = bx * NTHR + tid;
            if (gid < 32768) {
                float s = bcdn[gid & 511];
#pragma unroll
                for (int ks = 0; ks < 5; ks++) s += g_cdp[ks * 32768 + gid];
                g_cdn[gid] = fmaxf(s, 0.f);
            }
        }
        gsync(gs);
        if (bx < 80) {
            int tile = bx >> 1, kh = bx & 1;
            gemm2<0, 0>(g_cdn, nullptr, nullptr, 512,
                        emb, 512, 1 << 30, nullptr, 0,
                        tile * 128, Vsz, kh * 256, kh * 256 + 256,
                        g_lgp[kh], 5120, nullptr, nullptr, 0, sh);
        }
        gsync(gs);
        {
            int gid = bx * NTHR + tid;
            for (int e = gid; e < Bsz * Vsz; e += GRID * NTHR) {
                int m = e / Vsz, n = e - m * Vsz;
                out[((long)m * Tsz + (Tsz - 1)) * Vsz + n] =
                    g_lgp[0][m * 5120 + n] + g_lgp[1][m * 5120 + n] + bcls[n];
            }
        }
    }
}

extern "C" void kernel_launch(void* const* d_in, const int* in_sizes, int n_in,
                              void* d_out, int out_size) {
    mega<<<GRID, NTHR>>>(
        (const float*)d_in[0],  (const int*)d_in[1],   (const float*)d_in[2],
        (const float*)d_in[3],  (const float*)d_in[4],
        (const float*)d_in[5],  (const float*)d_in[6],
        (const float*)d_in[7],  (const float*)d_in[8],
        (const float*)d_in[9],  (const float*)d_in[10],
        (const float*)d_in[11], (const float*)d_in[12],
        (const float*)d_in[13], (const float*)d_in[14],
        (const float*)d_in[15], (const float*)d_in[16],
        (const float*)d_in[17], (const float*)d_in[18],
        (const float*)d_in[19], (float*)d_out);
}